// round 1
// baseline (speedup 1.0000x reference)
#include <cuda_runtime.h>
#include <math.h>

#define THREADS 256
#define BN 64          // nodes per block
#define NU 128         // MUL0
#define NV 32          // A
#define NW1 128        // stage-1 outputs
#define NW2 32         // stage-2 outputs
#define SPAD 65        // padded stride for transposed s / s_act
#define APAD 65        // padded stride for transposed attr

// shared memory layout (floats)
constexpr int OFF_ATTR = 0;                       // attrT: [v*APAD + n], 32*65
constexpr int OFF_ST   = OFF_ATTR + NV * APAD;    // sT:    [u*SPAD + n], 128*65
constexpr int OFF_T    = OFF_ST + NU * SPAD;      // t:     2 x [v*64 + n]
constexpr int OFF_W    = OFF_T + 2 * NV * BN;     // w:     2 x [v*128 + w] (stage2 uses first 1024)
constexpr int OFF_AT   = OFF_W + 2 * NV * NW1;    // aT:    [u*SPAD + n], 128*65
constexpr int OFF_HP   = OFF_AT + NU * SPAD;      // hpart: [g][n][w], 4*64*32
constexpr int OFF_H    = OFF_HP + 4 * BN * NW2;   // h:     [n*32 + w], 64*32
constexpr int OFF_W3   = OFF_H + BN * NW2;        // W3:    [k*32 + w], 1024
constexpr int OFF_B1   = OFF_W3 + NV * NV;        // 128
constexpr int OFF_B2   = OFF_B1 + NW1;            // 32
constexpr int OFF_B3   = OFF_B2 + NW2;            // 32
constexpr int OFF_W4   = OFF_B3 + NW2;            // 32
constexpr int OFF_B4   = OFF_W4 + NW2;            // 1
constexpr int SMEM_FLOATS = OFF_B4 + 4;
constexpr size_t SMEM_BYTES = (size_t)SMEM_FLOATS * sizeof(float);

__device__ __forceinline__ float silu_f(float x) {
    return x / (1.0f + __expf(-x));
}

extern __shared__ float smem[];

__global__ void __launch_bounds__(THREADS, 1) eq_fused(
    const float* __restrict__ node_vec,   // [N, 480]
    const float* __restrict__ attr_g,     // [N, 32]
    const float* __restrict__ W1s,        // [128, 32, 128]
    const float* __restrict__ b1s,        // [128]
    const float* __restrict__ W2,         // [128, 32, 32]
    const float* __restrict__ b2,         // [32]
    const float* __restrict__ W3,         // [32, 32]
    const float* __restrict__ b3,         // [32]
    const float* __restrict__ W4,         // [32]
    const float* __restrict__ b4,         // [1]
    float* __restrict__ out)              // [N]
{
    float* attrT  = smem + OFF_ATTR;
    float* sT     = smem + OFF_ST;
    float* t_sh   = smem + OFF_T;
    float* w_sh   = smem + OFF_W;
    float* aT     = smem + OFF_AT;
    float* hpart  = smem + OFF_HP;
    float* h_sh   = smem + OFF_H;
    float* w3_sh  = smem + OFF_W3;
    float* b1s_sh = smem + OFF_B1;
    float* b2_sh  = smem + OFF_B2;
    float* b3_sh  = smem + OFF_B3;
    float* w4_sh  = smem + OFF_W4;
    float* b4_sh  = smem + OFF_B4;

    const int tid = threadIdx.x;
    const int nb  = blockIdx.x * BN;

    // ---------------- load block inputs ----------------
    // attr: [64][32] contiguous -> transposed padded
    for (int i = tid; i < BN * NV / 4; i += THREADS) {
        int n = i >> 3;           // /(32/4)
        int c4 = i & 7;
        float4 v = *(const float4*)(attr_g + (size_t)(nb + n) * NV + c4 * 4);
        attrT[(c4 * 4 + 0) * APAD + n] = v.x;
        attrT[(c4 * 4 + 1) * APAD + n] = v.y;
        attrT[(c4 * 4 + 2) * APAD + n] = v.z;
        attrT[(c4 * 4 + 3) * APAD + n] = v.w;
    }
    // s: first 128 cols of stride-480 rows -> transposed padded
    for (int i = tid; i < BN * NU / 4; i += THREADS) {
        int r  = i >> 5;          // /(128/4)
        int c4 = i & 31;
        float4 v = *(const float4*)(node_vec + (size_t)(nb + r) * 480 + c4 * 4);
        sT[(c4 * 4 + 0) * SPAD + r] = v.x;
        sT[(c4 * 4 + 1) * SPAD + r] = v.y;
        sT[(c4 * 4 + 2) * SPAD + r] = v.z;
        sT[(c4 * 4 + 3) * SPAD + r] = v.w;
    }
    for (int i = tid; i < NV * NV / 4; i += THREADS)
        ((float4*)w3_sh)[i] = ((const float4*)W3)[i];
    if (tid < NW1) b1s_sh[tid] = b1s[tid];
    if (tid < NW2) { b2_sh[tid] = b2[tid]; b3_sh[tid] = b3[tid]; w4_sh[tid] = W4[tid]; }
    if (tid == 0) b4_sh[0] = b4[0];
    __syncthreads();

    // t-tile fill mapping (all 256 threads): fv = v, fn..fn+7 = nodes
    const int fv = tid >> 3;
    const int fn = (tid & 7) * 8;

    // =========== stage 1: s_mid[64][128], K = 128 u-chunks of 32 v ===========
    const int wt = tid & 31, nt = tid >> 5;
    const int w0 = wt * 4, n0 = nt * 8;

    float acc[8][4];
#pragma unroll
    for (int i = 0; i < 8; i++)
#pragma unroll
        for (int j = 0; j < 4; j++) acc[i][j] = 0.0f;

    // prologue: fill buffer 0 for u = 0
    {
#pragma unroll
        for (int j = 0; j < 8; ++j)
            t_sh[fv * BN + fn + j] = sT[fn + j] * attrT[fv * APAD + fn + j];
        const float4* wp = (const float4*)W1s;
#pragma unroll
        for (int j = 0; j < 4; ++j)
            ((float4*)w_sh)[tid + j * THREADS] = wp[tid + j * THREADS];
    }
    __syncthreads();

    for (int u = 0; u < NU; ++u) {
        const int cur = u & 1, nxt = cur ^ 1;
        float4 wreg[4];
        float  treg[8];
        const bool pf = (u + 1 < NU);
        if (pf) {
            const float4* wp = (const float4*)(W1s + (size_t)(u + 1) * (NV * NW1));
#pragma unroll
            for (int j = 0; j < 4; ++j) wreg[j] = wp[tid + j * THREADS];
#pragma unroll
            for (int j = 0; j < 8; ++j)
                treg[j] = sT[(u + 1) * SPAD + fn + j] * attrT[fv * APAD + fn + j];
        }
        const float* tb_ = t_sh + cur * (NV * BN);
        const float* wb_ = w_sh + cur * (NV * NW1);
#pragma unroll 8
        for (int v = 0; v < NV; ++v) {
            float4 ta = *(const float4*)(tb_ + v * BN + n0);
            float4 tb = *(const float4*)(tb_ + v * BN + n0 + 4);
            float4 wv = *(const float4*)(wb_ + v * NW1 + w0);
            float tv[8] = {ta.x, ta.y, ta.z, ta.w, tb.x, tb.y, tb.z, tb.w};
#pragma unroll
            for (int i = 0; i < 8; i++) {
                acc[i][0] += tv[i] * wv.x;
                acc[i][1] += tv[i] * wv.y;
                acc[i][2] += tv[i] * wv.z;
                acc[i][3] += tv[i] * wv.w;
            }
        }
        if (pf) {
            float* tn = t_sh + nxt * (NV * BN);
            float* wn = w_sh + nxt * (NV * NW1);
#pragma unroll
            for (int j = 0; j < 4; ++j) ((float4*)wn)[tid + j * THREADS] = wreg[j];
#pragma unroll
            for (int j = 0; j < 8; ++j) tn[fv * BN + fn + j] = treg[j];
        }
        __syncthreads();
    }

    // silu -> aT (transposed, padded)
    const float inv64 = 0.015625f;   // 1/sqrt(128*32)
#pragma unroll
    for (int j = 0; j < 4; ++j) {
        float bv = b1s_sh[w0 + j];
#pragma unroll
        for (int i = 0; i < 8; ++i) {
            float x = acc[i][j] * inv64 + bv;
            aT[(w0 + j) * SPAD + n0 + i] = silu_f(x);
        }
    }
    __syncthreads();

    // =========== stage 2: h[64][32], v split across 4 groups ===========
    const int g    = tid >> 6;
    const int l    = tid & 63;
    const int w0b  = (l & 7) * 4;
    const int n0b  = (l >> 3) * 8;
    const int vlo  = g * 8;

    float acc2[8][4];
#pragma unroll
    for (int i = 0; i < 8; i++)
#pragma unroll
        for (int j = 0; j < 4; j++) acc2[i][j] = 0.0f;

    // prologue fill (u = 0)
#pragma unroll
    for (int j = 0; j < 8; ++j)
        t_sh[fv * BN + fn + j] = aT[fn + j] * attrT[fv * APAD + fn + j];
    ((float4*)w_sh)[tid] = ((const float4*)W2)[tid];   // 1024 floats
    __syncthreads();

    for (int u = 0; u < NU; ++u) {
        const int cur = u & 1, nxt = cur ^ 1;
        float4 wreg2;
        float  treg[8];
        const bool pf = (u + 1 < NU);
        if (pf) {
            wreg2 = ((const float4*)(W2 + (size_t)(u + 1) * (NV * NW2)))[tid];
#pragma unroll
            for (int j = 0; j < 8; ++j)
                treg[j] = aT[(u + 1) * SPAD + fn + j] * attrT[fv * APAD + fn + j];
        }
        const float* tb_ = t_sh + cur * (NV * BN);
        const float* wb_ = w_sh + cur * (NV * NW1);
#pragma unroll
        for (int vv = 0; vv < 8; ++vv) {
            int v = vlo + vv;
            float4 ta = *(const float4*)(tb_ + v * BN + n0b);
            float4 tb = *(const float4*)(tb_ + v * BN + n0b + 4);
            float4 wv = *(const float4*)(wb_ + v * NW2 + w0b);
            float tv[8] = {ta.x, ta.y, ta.z, ta.w, tb.x, tb.y, tb.z, tb.w};
#pragma unroll
            for (int i = 0; i < 8; i++) {
                acc2[i][0] += tv[i] * wv.x;
                acc2[i][1] += tv[i] * wv.y;
                acc2[i][2] += tv[i] * wv.z;
                acc2[i][3] += tv[i] * wv.w;
            }
        }
        if (pf) {
            ((float4*)(w_sh + nxt * (NV * NW1)))[tid] = wreg2;
            float* tn = t_sh + nxt * (NV * BN);
#pragma unroll
            for (int j = 0; j < 8; ++j) tn[fv * BN + fn + j] = treg[j];
        }
        __syncthreads();
    }

    // write v-group partials
#pragma unroll
    for (int i = 0; i < 8; ++i) {
        float4 r = make_float4(acc2[i][0], acc2[i][1], acc2[i][2], acc2[i][3]);
        *(float4*)(hpart + g * (BN * NW2) + (n0b + i) * NW2 + w0b) = r;
    }
    __syncthreads();

    // reduce 4 partials + bias
    for (int f = tid; f < BN * NW2 / 4; f += THREADS) {
        float4 a = ((const float4*)hpart)[f];
        float4 b = ((const float4*)hpart)[512 + f];
        float4 c = ((const float4*)hpart)[1024 + f];
        float4 d = ((const float4*)hpart)[1536 + f];
        float4 bb = ((const float4*)b2_sh)[f & 7];
        float4 r;
        r.x = (a.x + b.x + c.x + d.x) * inv64 + bb.x;
        r.y = (a.y + b.y + c.y + d.y) * inv64 + bb.y;
        r.z = (a.z + b.z + c.z + d.z) * inv64 + bb.z;
        r.w = (a.w + b.w + c.w + d.w) * inv64 + bb.w;
        ((float4*)h_sh)[f] = r;
    }
    __syncthreads();

    // =========== stage 3/4: per-node 32x32 + 32x1 ===========
    if (tid < BN) {
        float h[32];
#pragma unroll
        for (int k = 0; k < 32; ++k) h[k] = h_sh[tid * 32 + k];
        const float inv_s32 = 0.17677669529663687f;   // 1/sqrt(32)
        float o = b4_sh[0];
#pragma unroll 4
        for (int w = 0; w < 32; ++w) {
            float z = 0.0f;
#pragma unroll
            for (int k = 0; k < 32; ++k) z += h[k] * w3_sh[k * 32 + w];
            z = z * inv_s32 + b3_sh[w];
            o += silu_f(z) * (w4_sh[w] * inv_s32);
        }
        out[nb + tid] = o;
    }
}

extern "C" void kernel_launch(void* const* d_in, const int* in_sizes, int n_in,
                              void* d_out, int out_size) {
    const float* node_vec = (const float*)d_in[0];
    const float* attr     = (const float*)d_in[1];
    const float* W1s      = (const float*)d_in[2];
    const float* b1s      = (const float*)d_in[3];
    // d_in[4..7] = W1g, b1g, W1v1, W1v2 : dead code in the reference
    const float* W2       = (const float*)d_in[8];
    const float* b2       = (const float*)d_in[9];
    const float* W3       = (const float*)d_in[10];
    const float* b3       = (const float*)d_in[11];
    const float* W4       = (const float*)d_in[12];
    const float* b4       = (const float*)d_in[13];
    float* out = (float*)d_out;

    const int N = out_size;          // 8192 nodes, one scalar each
    cudaFuncSetAttribute(eq_fused, cudaFuncAttributeMaxDynamicSharedMemorySize,
                         (int)SMEM_BYTES);
    dim3 grid(N / BN), block(THREADS);
    eq_fused<<<grid, block, SMEM_BYTES>>>(node_vec, attr, W1s, b1s,
                                          W2, b2, W3, b3, W4, b4, out);
}

// round 3
// speedup vs baseline: 1.7785x; 1.7785x over previous
#include <cuda_runtime.h>
#include <cuda_bf16.h>
#include <cstdint>

// ============================================================================
// Problem constants
// ============================================================================
#define NU 128         // MUL0
#define NV 32          // A
#define KTOT 4096      // NU*NV
#define MT 64          // nodes per block
#define KC 64          // K per chunk
#define NCHUNK 64      // KTOT/KC
#define THREADS 256

// pre-transposed / hi-lo split weights (scale 1/64 folded in)
__device__ __align__(16) __nv_bfloat16 g_W1T_hi[NU * KTOT];
__device__ __align__(16) __nv_bfloat16 g_W1T_lo[NU * KTOT];
__device__ __align__(16) __nv_bfloat16 g_W2T_hi[NV * KTOT];
__device__ __align__(16) __nv_bfloat16 g_W2T_lo[NV * KTOT];

// ---- smem layout (bytes) ----
constexpr uint32_t OFF_A    = 0;          // A tiles: [buf][hi/lo] 4 x 8192  = 32768
constexpr uint32_t OFF_B    = 32768;      // B tiles: [buf][hi/lo] 4 x 16384 = 65536
constexpr uint32_t OFF_S    = 98304;      // sT / aT fp32 [128u][65]  = 33280
constexpr uint32_t OFF_ATTR = 131584;     // attr fp32 [64n][36]      = 9216
constexpr uint32_t OFF_H    = 140800;     // h fp32 [64n][33]         = 8448
constexpr uint32_t OFF_W3   = 149248;     // 4096
constexpr uint32_t OFF_B1   = 153344;     // 512
constexpr uint32_t OFF_B2   = 153856;     // 128
constexpr uint32_t OFF_B3   = 153984;     // 128
constexpr uint32_t OFF_W4   = 154112;     // 128
constexpr uint32_t OFF_B4   = 154240;     // 16
constexpr uint32_t SMEM_BYTES = 154368;   // ~150.8 KB

extern __shared__ char smem_raw[];

__device__ __forceinline__ uint32_t smem_u32(const void* p) {
    uint32_t a;
    asm("{ .reg .u64 t; cvta.to.shared.u64 t, %1; cvt.u32.u64 %0, t; }" : "=r"(a) : "l"(p));
    return a;
}
__device__ __forceinline__ uint32_t swz(uint32_t o) { return o ^ ((o >> 3) & 0x70); }
__device__ __forceinline__ float silu_f(float x) { return x / (1.0f + __expf(-x)); }

#define STS128(r0, r1, r2, r3, sa) \
    asm volatile("st.shared.v4.b32 [%0], {%1, %2, %3, %4};" \
                 :: "r"(sa), "r"(r0), "r"(r1), "r"(r2), "r"(r3) : "memory")

__device__ __forceinline__ void ldsm4(uint32_t* r, uint32_t addr) {
    asm volatile("ldmatrix.sync.aligned.m8n8.x4.shared.b16 {%0,%1,%2,%3}, [%4];"
                 : "=r"(r[0]), "=r"(r[1]), "=r"(r[2]), "=r"(r[3]) : "r"(addr));
}
__device__ __forceinline__ void mma16816(float* c, const uint32_t* a,
                                         uint32_t b0, uint32_t b1) {
    asm volatile(
        "mma.sync.aligned.m16n8k16.row.col.f32.bf16.bf16.f32 "
        "{%0,%1,%2,%3}, {%4,%5,%6,%7}, {%8,%9}, {%0,%1,%2,%3};"
        : "+f"(c[0]), "+f"(c[1]), "+f"(c[2]), "+f"(c[3])
        : "r"(a[0]), "r"(a[1]), "r"(a[2]), "r"(a[3]), "r"(b0), "r"(b1));
}

// ============================================================================
// prep kernels: W[k][w] fp32 -> W^T[w][k] bf16 hi/lo, scale folded
// ============================================================================
__global__ void prep_w1(const float* __restrict__ W1s) {
    int i = blockIdx.x * blockDim.x + threadIdx.x;
    if (i >= KTOT * NU) return;
    int k = i >> 7, w = i & 127;
    float x = W1s[i] * 0.015625f;            // 1/sqrt(128*32)
    __nv_bfloat16 hi = __float2bfloat16(x);
    g_W1T_hi[w * KTOT + k] = hi;
    g_W1T_lo[w * KTOT + k] = __float2bfloat16(x - __bfloat162float(hi));
}
__global__ void prep_w2(const float* __restrict__ W2) {
    int i = blockIdx.x * blockDim.x + threadIdx.x;
    if (i >= KTOT * NV) return;
    int k = i >> 5, w = i & 31;
    float x = W2[i] * 0.015625f;
    __nv_bfloat16 hi = __float2bfloat16(x);
    g_W2T_hi[w * KTOT + k] = hi;
    g_W2T_lo[w * KTOT + k] = __float2bfloat16(x - __bfloat162float(hi));
}

// ============================================================================
// tile fills
// ============================================================================
__device__ __forceinline__ void fillA(int c, uint32_t aH, uint32_t aL,
                                      const float* srcT, const float* attrS, int tid) {
#pragma unroll
    for (int j = 0; j < 2; ++j) {
        int slot = tid + j * THREADS;        // 0..511
        int n = slot >> 3, kg = slot & 7;
        int u = (c << 1) + (kg >> 2);
        int vb = (kg & 3) << 3;
        float su = srcT[u * 65 + n];
        float4 a0 = *(const float4*)(attrS + n * 36 + vb);
        float4 a1 = *(const float4*)(attrS + n * 36 + vb + 4);
        float v[8] = {a0.x, a0.y, a0.z, a0.w, a1.x, a1.y, a1.z, a1.w};
        uint32_t hb[4], lb[4];
#pragma unroll
        for (int q = 0; q < 4; ++q) {
            float x0 = su * v[2 * q], x1 = su * v[2 * q + 1];
            __nv_bfloat162 h2 = __float22bfloat162_rn(make_float2(x0, x1));
            float r0 = x0 - __bfloat162float(h2.x);
            float r1 = x1 - __bfloat162float(h2.y);
            __nv_bfloat162 l2 = __float22bfloat162_rn(make_float2(r0, r1));
            hb[q] = *reinterpret_cast<uint32_t*>(&h2);
            lb[q] = *reinterpret_cast<uint32_t*>(&l2);
        }
        uint32_t sw = swz((uint32_t)(n * 128 + (kg << 4)));
        STS128(hb[0], hb[1], hb[2], hb[3], aH + sw);
        STS128(lb[0], lb[1], lb[2], lb[3], aL + sw);
    }
}

template <int BROWS>
__device__ __forceinline__ void fillB(int c, uint32_t bH, uint32_t bL,
                                      const __nv_bfloat16* gHi,
                                      const __nv_bfloat16* gLo, int tid) {
#pragma unroll
    for (int j = 0; j < (BROWS * 16) / THREADS; ++j) {
        int slot = tid + j * THREADS;        // [0, BROWS*16)
        int hl = (slot >= BROWS * 8) ? 1 : 0;
        int s2 = slot - hl * BROWS * 8;
        int row = s2 >> 3, kg = s2 & 7;
        uint4 val = ((const uint4*)(hl ? gLo : gHi))[row * 512 + c * 8 + kg];
        uint32_t sw = swz((uint32_t)(row * 128 + (kg << 4)));
        STS128(val.x, val.y, val.z, val.w, (hl ? bL : bH) + sw);
    }
}

// ============================================================================
// main fused kernel: one block = 64 nodes
// ============================================================================
__global__ void __launch_bounds__(THREADS, 1)
eq_hmma(const float* __restrict__ node_vec,   // [N,480]
        const float* __restrict__ attr_g,     // [N,32]
        const float* __restrict__ b1s,        // [128]
        const float* __restrict__ b2,         // [32]
        const float* __restrict__ W3,         // [32,32]
        const float* __restrict__ b3,         // [32]
        const float* __restrict__ W4,         // [32]
        const float* __restrict__ b4,         // [1]
        float* __restrict__ out)              // [N]
{
    const int tid  = threadIdx.x;
    const int wid  = tid >> 5;
    const int lane = tid & 31;
    const int nb   = blockIdx.x * MT;
    const uint32_t sb = smem_u32(smem_raw);

    float* sT    = (float*)(smem_raw + OFF_S);     // [u][65]
    float* attrS = (float*)(smem_raw + OFF_ATTR);  // [n][36]
    float* hS    = (float*)(smem_raw + OFF_H);     // [n][33]
    float* w3S   = (float*)(smem_raw + OFF_W3);
    float* b1S   = (float*)(smem_raw + OFF_B1);
    float* b2S   = (float*)(smem_raw + OFF_B2);
    float* b3S   = (float*)(smem_raw + OFF_B3);
    float* w4S   = (float*)(smem_raw + OFF_W4);
    float* b4S   = (float*)(smem_raw + OFF_B4);

    // ---- load block inputs ----
#pragma unroll
    for (int j = 0; j < 8; ++j) {              // s -> transposed [u][65]
        int i = tid + j * THREADS;             // 2048 float4 slots
        int n = i >> 5, c4 = i & 31;
        float4 v = *(const float4*)(node_vec + (size_t)(nb + n) * 480 + c4 * 4);
        sT[(c4 * 4 + 0) * 65 + n] = v.x;
        sT[(c4 * 4 + 1) * 65 + n] = v.y;
        sT[(c4 * 4 + 2) * 65 + n] = v.z;
        sT[(c4 * 4 + 3) * 65 + n] = v.w;
    }
#pragma unroll
    for (int j = 0; j < 2; ++j) {              // attr -> [n][36]
        int i = tid + j * THREADS;             // 512 float4 slots
        int n = i >> 3, c4 = i & 7;
        *(float4*)(attrS + n * 36 + c4 * 4) =
            *(const float4*)(attr_g + (size_t)(nb + n) * NV + c4 * 4);
    }
    if (tid < 256) ((float4*)w3S)[tid] = ((const float4*)W3)[tid];
    if (tid < 128) b1S[tid] = b1s[tid];
    if (tid < 32) { b2S[tid] = b2[tid]; b3S[tid] = b3[tid]; w4S[tid] = W4[tid]; }
    if (tid == 0) b4S[0] = b4[0];
    __syncthreads();

    // ldmatrix per-lane offsets
    const uint32_t rowA = (uint32_t)((((lane >> 3) & 1) << 3) + (lane & 7));
    const uint32_t colA = (uint32_t)((lane >> 4) << 4);
    const uint32_t rowB = (uint32_t)(((lane >> 4) << 3) + (lane & 7));
    const uint32_t colB = (uint32_t)(((lane >> 3) & 1) << 4);

    // tile bases
    auto tA = [&](int buf, int h) { return sb + OFF_A + (uint32_t)((buf * 2 + h) * 8192); };
    auto tB = [&](int buf, int h) { return sb + OFF_B + (uint32_t)((buf * 2 + h) * 16384); };

    // ======================= stage 1: C[64,128], K=4096 =======================
    {
        const int m0 = (wid >> 2) * 32;
        const int n0 = (wid & 3) * 32;
        float acc[2][4][4];
#pragma unroll
        for (int a = 0; a < 2; ++a)
#pragma unroll
            for (int b = 0; b < 4; ++b)
#pragma unroll
                for (int q = 0; q < 4; ++q) acc[a][b][q] = 0.0f;

        fillA(0, tA(0, 0), tA(0, 1), sT, attrS, tid);
        fillB<128>(0, tB(0, 0), tB(0, 1), g_W1T_hi, g_W1T_lo, tid);
        __syncthreads();

        for (int c = 0; c < NCHUNK; ++c) {
            const int cb = c & 1;
            if (c + 1 < NCHUNK) {
                fillA(c + 1, tA(cb ^ 1, 0), tA(cb ^ 1, 1), sT, attrS, tid);
                fillB<128>(c + 1, tB(cb ^ 1, 0), tB(cb ^ 1, 1), g_W1T_hi, g_W1T_lo, tid);
            }
            const uint32_t aHb = tA(cb, 0), aLb = tA(cb, 1);
            const uint32_t bHb = tB(cb, 0), bLb = tB(cb, 1);
#pragma unroll
            for (int ks = 0; ks < 4; ++ks) {
                uint32_t aH[2][4], aL[2][4], bH[2][4], bL[2][4];
#pragma unroll
                for (int mf = 0; mf < 2; ++mf) {
                    uint32_t off = swz((uint32_t)((m0 + mf * 16 + rowA) * 128 + ks * 32 + colA));
                    ldsm4(aH[mf], aHb + off);
                    ldsm4(aL[mf], aLb + off);
                }
#pragma unroll
                for (int nbk = 0; nbk < 2; ++nbk) {
                    uint32_t off = swz((uint32_t)((n0 + nbk * 16 + rowB) * 128 + ks * 32 + colB));
                    ldsm4(bH[nbk], bHb + off);
                    ldsm4(bL[nbk], bLb + off);
                }
#pragma unroll
                for (int mf = 0; mf < 2; ++mf)
#pragma unroll
                    for (int nf = 0; nf < 4; ++nf) {
                        uint32_t h0 = bH[nf >> 1][(nf & 1) * 2], h1 = bH[nf >> 1][(nf & 1) * 2 + 1];
                        uint32_t l0 = bL[nf >> 1][(nf & 1) * 2], l1 = bL[nf >> 1][(nf & 1) * 2 + 1];
                        mma16816(acc[mf][nf], aH[mf], h0, h1);
                        mma16816(acc[mf][nf], aH[mf], l0, l1);
                        mma16816(acc[mf][nf], aL[mf], h0, h1);
                    }
            }
            __syncthreads();
        }

        // epilogue 1: silu(c + b1) -> sT[w][node] (overwrites s, same layout)
#pragma unroll
        for (int mf = 0; mf < 2; ++mf)
#pragma unroll
            for (int nf = 0; nf < 4; ++nf) {
                int m = m0 + mf * 16 + (lane >> 2);
                int w = n0 + nf * 8 + ((lane & 3) << 1);
                float* cc = acc[mf][nf];
                sT[w * 65 + m]           = silu_f(cc[0] + b1S[w]);
                sT[(w + 1) * 65 + m]     = silu_f(cc[1] + b1S[w + 1]);
                sT[w * 65 + m + 8]       = silu_f(cc[2] + b1S[w]);
                sT[(w + 1) * 65 + m + 8] = silu_f(cc[3] + b1S[w + 1]);
            }
        __syncthreads();
    }

    // ======================= stage 2: C[64,32], K=4096 =======================
    {
        const int m0 = (wid >> 1) * 16;
        const int n0 = (wid & 1) * 16;
        float acc[2][4];
#pragma unroll
        for (int b = 0; b < 2; ++b)
#pragma unroll
            for (int q = 0; q < 4; ++q) acc[b][q] = 0.0f;

        fillA(0, tA(0, 0), tA(0, 1), sT, attrS, tid);
        fillB<32>(0, tB(0, 0), tB(0, 1), g_W2T_hi, g_W2T_lo, tid);
        __syncthreads();

        for (int c = 0; c < NCHUNK; ++c) {
            const int cb = c & 1;
            if (c + 1 < NCHUNK) {
                fillA(c + 1, tA(cb ^ 1, 0), tA(cb ^ 1, 1), sT, attrS, tid);
                fillB<32>(c + 1, tB(cb ^ 1, 0), tB(cb ^ 1, 1), g_W2T_hi, g_W2T_lo, tid);
            }
            const uint32_t aHb = tA(cb, 0), aLb = tA(cb, 1);
            const uint32_t bHb = tB(cb, 0), bLb = tB(cb, 1);
#pragma unroll
            for (int ks = 0; ks < 4; ++ks) {
                uint32_t aH[4], aL[4], bH[4], bL[4];
                {
                    uint32_t off = swz((uint32_t)((m0 + rowA) * 128 + ks * 32 + colA));
                    ldsm4(aH, aHb + off);
                    ldsm4(aL, aLb + off);
                }
                {
                    uint32_t off = swz((uint32_t)((n0 + rowB) * 128 + ks * 32 + colB));
                    ldsm4(bH, bHb + off);
                    ldsm4(bL, bLb + off);
                }
#pragma unroll
                for (int nf = 0; nf < 2; ++nf) {
                    uint32_t h0 = bH[nf * 2], h1 = bH[nf * 2 + 1];
                    uint32_t l0 = bL[nf * 2], l1 = bL[nf * 2 + 1];
                    mma16816(acc[nf], aH, h0, h1);
                    mma16816(acc[nf], aH, l0, l1);
                    mma16816(acc[nf], aL, h0, h1);
                }
            }
            __syncthreads();
        }

        // epilogue 2: h = c + b2 -> hS[node][33]
#pragma unroll
        for (int nf = 0; nf < 2; ++nf) {
            int m = m0 + (lane >> 2);
            int w = n0 + nf * 8 + ((lane & 3) << 1);
            float* cc = acc[nf];
            hS[m * 33 + w]           = cc[0] + b2S[w];
            hS[m * 33 + w + 1]       = cc[1] + b2S[w + 1];
            hS[(m + 8) * 33 + w]     = cc[2] + b2S[w];
            hS[(m + 8) * 33 + w + 1] = cc[3] + b2S[w + 1];
        }
        __syncthreads();
    }

    // ======================= stage 3/4: per-node tail =======================
    if (tid < MT) {
        float h[32];
#pragma unroll
        for (int k = 0; k < 32; ++k) h[k] = hS[tid * 33 + k];
        const float inv32 = 0.17677669529663687f;  // 1/sqrt(32)
        float o = b4S[0];
#pragma unroll 4
        for (int w = 0; w < 32; ++w) {
            float z = 0.0f;
#pragma unroll
            for (int k = 0; k < 32; ++k) z += h[k] * w3S[k * 32 + w];
            z = z * inv32 + b3S[w];
            o += silu_f(z) * (w4S[w] * inv32);
        }
        out[nb + tid] = o;
    }
}

// ============================================================================
extern "C" void kernel_launch(void* const* d_in, const int* in_sizes, int n_in,
                              void* d_out, int out_size) {
    const float* node_vec = (const float*)d_in[0];
    const float* attr     = (const float*)d_in[1];
    const float* W1s      = (const float*)d_in[2];
    const float* b1s      = (const float*)d_in[3];
    // d_in[4..7] = W1g, b1g, W1v1, W1v2 : dead in the reference
    const float* W2       = (const float*)d_in[8];
    const float* b2       = (const float*)d_in[9];
    const float* W3       = (const float*)d_in[10];
    const float* b3       = (const float*)d_in[11];
    const float* W4       = (const float*)d_in[12];
    const float* b4       = (const float*)d_in[13];
    float* out = (float*)d_out;

    const int N = out_size;                    // 8192

    prep_w1<<<(KTOT * NU + 255) / 256, 256>>>(W1s);
    prep_w2<<<(KTOT * NV + 255) / 256, 256>>>(W2);

    cudaFuncSetAttribute(eq_hmma, cudaFuncAttributeMaxDynamicSharedMemorySize,
                         (int)SMEM_BYTES);
    eq_hmma<<<N / MT, THREADS, SMEM_BYTES>>>(node_vec, attr, b1s, b2, W3, b3, W4, b4, out);
}

// round 4
// speedup vs baseline: 2.2651x; 1.2736x over previous
#include <cuda_runtime.h>
#include <cuda_bf16.h>
#include <cstdint>

// ============================================================================
// Problem constants
// ============================================================================
#define NU 128         // MUL0
#define NV 32          // A
#define KTOT 4096      // NU*NV
#define MT 64          // nodes per block
#define KC 64          // K per chunk
#define NCHUNK 64      // KTOT/KC
#define THREADS 512    // 8 consumer warps + 8 producer warps
#define PT 256         // producer thread count

// pre-transposed / hi-lo split weights (scale 1/64 folded in)
__device__ __align__(16) __nv_bfloat16 g_W1T_hi[NU * KTOT];
__device__ __align__(16) __nv_bfloat16 g_W1T_lo[NU * KTOT];
__device__ __align__(16) __nv_bfloat16 g_W2T_hi[NV * KTOT];
__device__ __align__(16) __nv_bfloat16 g_W2T_lo[NV * KTOT];

// ---- smem layout (bytes) ----
constexpr uint32_t OFF_A    = 0;          // A tiles: [buf][hi/lo] 4 x 8192  = 32768
constexpr uint32_t OFF_B    = 32768;      // B tiles: [buf][hi/lo] 4 x 16384 = 65536
constexpr uint32_t OFF_S    = 98304;      // sT / aT fp32 [128u][65]  = 33280
constexpr uint32_t OFF_ATTR = 131584;     // attr fp32 [64n][36]      = 9216
constexpr uint32_t OFF_H    = 140800;     // h fp32 [64n][33]         = 8448
constexpr uint32_t OFF_W3   = 149248;     // 4096
constexpr uint32_t OFF_B1   = 153344;     // 512
constexpr uint32_t OFF_B2   = 153856;     // 128
constexpr uint32_t OFF_B3   = 153984;     // 128
constexpr uint32_t OFF_W4   = 154112;     // 128
constexpr uint32_t OFF_B4   = 154240;     // 16
constexpr uint32_t SMEM_BYTES = 154368;   // ~150.8 KB

extern __shared__ char smem_raw[];

__device__ __forceinline__ uint32_t smem_u32(const void* p) {
    uint32_t a;
    asm("{ .reg .u64 t; cvta.to.shared.u64 t, %1; cvt.u32.u64 %0, t; }" : "=r"(a) : "l"(p));
    return a;
}
__device__ __forceinline__ uint32_t swz(uint32_t o) { return o ^ ((o >> 3) & 0x70); }
__device__ __forceinline__ float silu_f(float x) { return x / (1.0f + __expf(-x)); }

#define STS128(r0, r1, r2, r3, sa) \
    asm volatile("st.shared.v4.b32 [%0], {%1, %2, %3, %4};" \
                 :: "r"(sa), "r"(r0), "r"(r1), "r"(r2), "r"(r3) : "memory")

__device__ __forceinline__ void ldsm4(uint32_t* r, uint32_t addr) {
    asm volatile("ldmatrix.sync.aligned.m8n8.x4.shared.b16 {%0,%1,%2,%3}, [%4];"
                 : "=r"(r[0]), "=r"(r[1]), "=r"(r[2]), "=r"(r[3]) : "r"(addr));
}
__device__ __forceinline__ void mma16816(float* c, const uint32_t* a,
                                         uint32_t b0, uint32_t b1) {
    asm volatile(
        "mma.sync.aligned.m16n8k16.row.col.f32.bf16.bf16.f32 "
        "{%0,%1,%2,%3}, {%4,%5,%6,%7}, {%8,%9}, {%0,%1,%2,%3};"
        : "+f"(c[0]), "+f"(c[1]), "+f"(c[2]), "+f"(c[3])
        : "r"(a[0]), "r"(a[1]), "r"(a[2]), "r"(a[3]), "r"(b0), "r"(b1));
}

// ============================================================================
// prep kernels: W[k][w] fp32 -> W^T[w][k] bf16 hi/lo via smem tiled transpose
// ============================================================================
__global__ void __launch_bounds__(256) prep_w1(const float* __restrict__ W1s) {
    __shared__ float tile[64][65];
    const int t = threadIdx.x;
    const int k0 = blockIdx.x * 64;        // grid.x = 64
    const int w0 = blockIdx.y * 64;        // grid.y = 2
    // load 64 k-rows x 64 w (coalesced float4)
#pragma unroll
    for (int it = 0; it < 4; ++it) {
        int s = it * 256 + t;
        int r = s >> 4, q = s & 15;
        float4 v = *(const float4*)(W1s + (size_t)(k0 + r) * NU + w0 + q * 4);
        tile[r][q * 4 + 0] = v.x; tile[r][q * 4 + 1] = v.y;
        tile[r][q * 4 + 2] = v.z; tile[r][q * 4 + 3] = v.w;
    }
    __syncthreads();
    // write transposed: uint4 (8 bf16) along k, coalesced
#pragma unroll
    for (int half = 0; half < 2; ++half) {
        int w = half * 32 + (t >> 3);
        int kq = t & 7;
        uint32_t hb[4], lb[4];
#pragma unroll
        for (int q = 0; q < 4; ++q) {
            float x0 = tile[kq * 8 + 2 * q][w]     * 0.015625f;
            float x1 = tile[kq * 8 + 2 * q + 1][w] * 0.015625f;
            __nv_bfloat162 h2 = __float22bfloat162_rn(make_float2(x0, x1));
            float r0 = x0 - __bfloat162float(h2.x);
            float r1 = x1 - __bfloat162float(h2.y);
            __nv_bfloat162 l2 = __float22bfloat162_rn(make_float2(r0, r1));
            hb[q] = *reinterpret_cast<uint32_t*>(&h2);
            lb[q] = *reinterpret_cast<uint32_t*>(&l2);
        }
        ((uint4*)(g_W1T_hi + (size_t)(w0 + w) * KTOT + k0))[kq] =
            make_uint4(hb[0], hb[1], hb[2], hb[3]);
        ((uint4*)(g_W1T_lo + (size_t)(w0 + w) * KTOT + k0))[kq] =
            make_uint4(lb[0], lb[1], lb[2], lb[3]);
    }
}

__global__ void __launch_bounds__(256) prep_w2(const float* __restrict__ W2) {
    __shared__ float tile[64][33];
    const int t = threadIdx.x;
    const int k0 = blockIdx.x * 64;        // grid.x = 64
#pragma unroll
    for (int it = 0; it < 2; ++it) {
        int s = it * 256 + t;
        int r = s >> 3, q = s & 7;
        float4 v = *(const float4*)(W2 + (size_t)(k0 + r) * NV + q * 4);
        tile[r][q * 4 + 0] = v.x; tile[r][q * 4 + 1] = v.y;
        tile[r][q * 4 + 2] = v.z; tile[r][q * 4 + 3] = v.w;
    }
    __syncthreads();
    {
        int w = t >> 3;                    // 32 w rows
        int kq = t & 7;
        uint32_t hb[4], lb[4];
#pragma unroll
        for (int q = 0; q < 4; ++q) {
            float x0 = tile[kq * 8 + 2 * q][w]     * 0.015625f;
            float x1 = tile[kq * 8 + 2 * q + 1][w] * 0.015625f;
            __nv_bfloat162 h2 = __float22bfloat162_rn(make_float2(x0, x1));
            float r0 = x0 - __bfloat162float(h2.x);
            float r1 = x1 - __bfloat162float(h2.y);
            __nv_bfloat162 l2 = __float22bfloat162_rn(make_float2(r0, r1));
            hb[q] = *reinterpret_cast<uint32_t*>(&h2);
            lb[q] = *reinterpret_cast<uint32_t*>(&l2);
        }
        ((uint4*)(g_W2T_hi + (size_t)w * KTOT + k0))[kq] =
            make_uint4(hb[0], hb[1], hb[2], hb[3]);
        ((uint4*)(g_W2T_lo + (size_t)w * KTOT + k0))[kq] =
            make_uint4(lb[0], lb[1], lb[2], lb[3]);
    }
}

// ============================================================================
// tile fills (producer warps, ptid in [0,256))
// ============================================================================
__device__ __forceinline__ void fillA(int c, uint32_t aH, uint32_t aL,
                                      const float* srcT, const float* attrS, int ptid) {
#pragma unroll
    for (int j = 0; j < 2; ++j) {
        int slot = ptid + j * PT;            // 0..511
        int n = slot >> 3, kg = slot & 7;
        int u = (c << 1) + (kg >> 2);
        int vb = (kg & 3) << 3;
        float su = srcT[u * 65 + n];
        float4 a0 = *(const float4*)(attrS + n * 36 + vb);
        float4 a1 = *(const float4*)(attrS + n * 36 + vb + 4);
        float v[8] = {a0.x, a0.y, a0.z, a0.w, a1.x, a1.y, a1.z, a1.w};
        uint32_t hb[4], lb[4];
#pragma unroll
        for (int q = 0; q < 4; ++q) {
            float x0 = su * v[2 * q], x1 = su * v[2 * q + 1];
            __nv_bfloat162 h2 = __float22bfloat162_rn(make_float2(x0, x1));
            float r0 = x0 - __bfloat162float(h2.x);
            float r1 = x1 - __bfloat162float(h2.y);
            __nv_bfloat162 l2 = __float22bfloat162_rn(make_float2(r0, r1));
            hb[q] = *reinterpret_cast<uint32_t*>(&h2);
            lb[q] = *reinterpret_cast<uint32_t*>(&l2);
        }
        uint32_t sw = swz((uint32_t)(n * 128 + (kg << 4)));
        STS128(hb[0], hb[1], hb[2], hb[3], aH + sw);
        STS128(lb[0], lb[1], lb[2], lb[3], aL + sw);
    }
}

template <int BROWS>
__device__ __forceinline__ void fillB(int c, uint32_t bH, uint32_t bL,
                                      const __nv_bfloat16* gHi,
                                      const __nv_bfloat16* gLo, int ptid) {
#pragma unroll
    for (int j = 0; j < (BROWS * 16) / PT; ++j) {
        int slot = ptid + j * PT;            // [0, BROWS*16)
        int hl = (slot >= BROWS * 8) ? 1 : 0;
        int s2 = slot - hl * BROWS * 8;
        int row = s2 >> 3, kg = s2 & 7;
        uint4 val = ((const uint4*)(hl ? gLo : gHi))[row * 512 + c * 8 + kg];
        uint32_t sw = swz((uint32_t)(row * 128 + (kg << 4)));
        STS128(val.x, val.y, val.z, val.w, (hl ? bL : bH) + sw);
    }
}

// ============================================================================
// main fused kernel: one block = 64 nodes; warps 0-7 MMA, warps 8-15 fill
// ============================================================================
__global__ void __launch_bounds__(THREADS, 1)
eq_hmma(const float* __restrict__ node_vec,   // [N,480]
        const float* __restrict__ attr_g,     // [N,32]
        const float* __restrict__ b1s,        // [128]
        const float* __restrict__ b2,         // [32]
        const float* __restrict__ W3,         // [32,32]
        const float* __restrict__ b3,         // [32]
        const float* __restrict__ W4,         // [32]
        const float* __restrict__ b4,         // [1]
        float* __restrict__ out)              // [N]
{
    const int tid  = threadIdx.x;
    const int wid  = tid >> 5;
    const int lane = tid & 31;
    const int nb   = blockIdx.x * MT;
    const uint32_t sb = smem_u32(smem_raw);
    const bool producer = (wid >= 8);
    const int ptid = tid - 256;

    float* sT    = (float*)(smem_raw + OFF_S);     // [u][65]
    float* attrS = (float*)(smem_raw + OFF_ATTR);  // [n][36]
    float* hS    = (float*)(smem_raw + OFF_H);     // [n][33]
    float* w3S   = (float*)(smem_raw + OFF_W3);
    float* b1S   = (float*)(smem_raw + OFF_B1);
    float* b2S   = (float*)(smem_raw + OFF_B2);
    float* b3S   = (float*)(smem_raw + OFF_B3);
    float* w4S   = (float*)(smem_raw + OFF_W4);
    float* b4S   = (float*)(smem_raw + OFF_B4);

    // ---- load block inputs (all 512 threads) ----
#pragma unroll
    for (int j = 0; j < 4; ++j) {              // s -> transposed [u][65]
        int i = tid + j * THREADS;             // 2048 float4 slots
        int n = i >> 5, c4 = i & 31;
        float4 v = *(const float4*)(node_vec + (size_t)(nb + n) * 480 + c4 * 4);
        sT[(c4 * 4 + 0) * 65 + n] = v.x;
        sT[(c4 * 4 + 1) * 65 + n] = v.y;
        sT[(c4 * 4 + 2) * 65 + n] = v.z;
        sT[(c4 * 4 + 3) * 65 + n] = v.w;
    }
    if (tid < 512) {                           // attr -> [n][36] (512 float4 slots)
        int n = tid >> 3, c4 = tid & 7;
        *(float4*)(attrS + n * 36 + c4 * 4) =
            *(const float4*)(attr_g + (size_t)(nb + n) * NV + c4 * 4);
    }
    if (tid < 256) ((float4*)w3S)[tid] = ((const float4*)W3)[tid];
    if (tid < 128) b1S[tid] = b1s[tid];
    if (tid < 32) { b2S[tid] = b2[tid]; b3S[tid] = b3[tid]; w4S[tid] = W4[tid]; }
    if (tid == 0) b4S[0] = b4[0];
    __syncthreads();

    // ldmatrix per-lane offsets
    const uint32_t rowA = (uint32_t)((((lane >> 3) & 1) << 3) + (lane & 7));
    const uint32_t colA = (uint32_t)((lane >> 4) << 4);
    const uint32_t rowB = (uint32_t)(((lane >> 4) << 3) + (lane & 7));
    const uint32_t colB = (uint32_t)(((lane >> 3) & 1) << 4);

    auto tA = [&](int buf, int h) { return sb + OFF_A + (uint32_t)((buf * 2 + h) * 8192); };
    auto tB = [&](int buf, int h) { return sb + OFF_B + (uint32_t)((buf * 2 + h) * 16384); };

    // ======================= stage 1: C[64,128], K=4096 =======================
    {
        const int m0 = (wid >> 2) * 32;        // consumers only (wid<8)
        const int n0 = (wid & 3) * 32;
        float acc[2][4][4];
#pragma unroll
        for (int a = 0; a < 2; ++a)
#pragma unroll
            for (int b = 0; b < 4; ++b)
#pragma unroll
                for (int q = 0; q < 4; ++q) acc[a][b][q] = 0.0f;

        if (producer) {
            fillA(0, tA(0, 0), tA(0, 1), sT, attrS, ptid);
            fillB<128>(0, tB(0, 0), tB(0, 1), g_W1T_hi, g_W1T_lo, ptid);
        }
        __syncthreads();

        for (int c = 0; c < NCHUNK; ++c) {
            const int cb = c & 1;
            if (producer) {
                if (c + 1 < NCHUNK) {
                    fillA(c + 1, tA(cb ^ 1, 0), tA(cb ^ 1, 1), sT, attrS, ptid);
                    fillB<128>(c + 1, tB(cb ^ 1, 0), tB(cb ^ 1, 1), g_W1T_hi, g_W1T_lo, ptid);
                }
            } else {
                const uint32_t aHb = tA(cb, 0), aLb = tA(cb, 1);
                const uint32_t bHb = tB(cb, 0), bLb = tB(cb, 1);
#pragma unroll
                for (int ks = 0; ks < 4; ++ks) {
                    uint32_t aH[2][4], aL[2][4], bH[2][4], bL[2][4];
#pragma unroll
                    for (int mf = 0; mf < 2; ++mf) {
                        uint32_t off = swz((uint32_t)((m0 + mf * 16 + rowA) * 128 + ks * 32 + colA));
                        ldsm4(aH[mf], aHb + off);
                        ldsm4(aL[mf], aLb + off);
                    }
#pragma unroll
                    for (int nbk = 0; nbk < 2; ++nbk) {
                        uint32_t off = swz((uint32_t)((n0 + nbk * 16 + rowB) * 128 + ks * 32 + colB));
                        ldsm4(bH[nbk], bHb + off);
                        ldsm4(bL[nbk], bLb + off);
                    }
#pragma unroll
                    for (int mf = 0; mf < 2; ++mf)
#pragma unroll
                        for (int nf = 0; nf < 4; ++nf) {
                            uint32_t h0 = bH[nf >> 1][(nf & 1) * 2], h1 = bH[nf >> 1][(nf & 1) * 2 + 1];
                            uint32_t l0 = bL[nf >> 1][(nf & 1) * 2], l1 = bL[nf >> 1][(nf & 1) * 2 + 1];
                            mma16816(acc[mf][nf], aH[mf], h0, h1);
                            mma16816(acc[mf][nf], aH[mf], l0, l1);
                            mma16816(acc[mf][nf], aL[mf], h0, h1);
                        }
                }
            }
            __syncthreads();
        }

        // epilogue 1: silu(c + b1) -> sT[w][node] (consumers)
        if (!producer) {
#pragma unroll
            for (int mf = 0; mf < 2; ++mf)
#pragma unroll
                for (int nf = 0; nf < 4; ++nf) {
                    int m = m0 + mf * 16 + (lane >> 2);
                    int w = n0 + nf * 8 + ((lane & 3) << 1);
                    float* cc = acc[mf][nf];
                    sT[w * 65 + m]           = silu_f(cc[0] + b1S[w]);
                    sT[(w + 1) * 65 + m]     = silu_f(cc[1] + b1S[w + 1]);
                    sT[w * 65 + m + 8]       = silu_f(cc[2] + b1S[w]);
                    sT[(w + 1) * 65 + m + 8] = silu_f(cc[3] + b1S[w + 1]);
                }
        }
        __syncthreads();
    }

    // ======================= stage 2: C[64,32], K=4096 =======================
    {
        const int m0 = (wid >> 1) * 16;
        const int n0 = (wid & 1) * 16;
        float acc[2][4];
#pragma unroll
        for (int b = 0; b < 2; ++b)
#pragma unroll
            for (int q = 0; q < 4; ++q) acc[b][q] = 0.0f;

        if (producer) {
            fillA(0, tA(0, 0), tA(0, 1), sT, attrS, ptid);
            fillB<32>(0, tB(0, 0), tB(0, 1), g_W2T_hi, g_W2T_lo, ptid);
        }
        __syncthreads();

        for (int c = 0; c < NCHUNK; ++c) {
            const int cb = c & 1;
            if (producer) {
                if (c + 1 < NCHUNK) {
                    fillA(c + 1, tA(cb ^ 1, 0), tA(cb ^ 1, 1), sT, attrS, ptid);
                    fillB<32>(c + 1, tB(cb ^ 1, 0), tB(cb ^ 1, 1), g_W2T_hi, g_W2T_lo, ptid);
                }
            } else {
                const uint32_t aHb = tA(cb, 0), aLb = tA(cb, 1);
                const uint32_t bHb = tB(cb, 0), bLb = tB(cb, 1);
#pragma unroll
                for (int ks = 0; ks < 4; ++ks) {
                    uint32_t aH[4], aL[4], bH[4], bL[4];
                    {
                        uint32_t off = swz((uint32_t)((m0 + rowA) * 128 + ks * 32 + colA));
                        ldsm4(aH, aHb + off);
                        ldsm4(aL, aLb + off);
                    }
                    {
                        uint32_t off = swz((uint32_t)((n0 + rowB) * 128 + ks * 32 + colB));
                        ldsm4(bH, bHb + off);
                        ldsm4(bL, bLb + off);
                    }
#pragma unroll
                    for (int nf = 0; nf < 2; ++nf) {
                        uint32_t h0 = bH[nf * 2], h1 = bH[nf * 2 + 1];
                        uint32_t l0 = bL[nf * 2], l1 = bL[nf * 2 + 1];
                        mma16816(acc[nf], aH, h0, h1);
                        mma16816(acc[nf], aH, l0, l1);
                        mma16816(acc[nf], aL, h0, h1);
                    }
                }
            }
            __syncthreads();
        }

        // epilogue 2: h = c + b2 -> hS[node][33]
        if (!producer) {
#pragma unroll
            for (int nf = 0; nf < 2; ++nf) {
                int m = m0 + (lane >> 2);
                int w = n0 + nf * 8 + ((lane & 3) << 1);
                float* cc = acc[nf];
                hS[m * 33 + w]           = cc[0] + b2S[w];
                hS[m * 33 + w + 1]       = cc[1] + b2S[w + 1];
                hS[(m + 8) * 33 + w]     = cc[2] + b2S[w];
                hS[(m + 8) * 33 + w + 1] = cc[3] + b2S[w + 1];
            }
        }
        __syncthreads();
    }

    // ======================= stage 3/4: per-node tail =======================
    if (tid < MT) {
        float h[32];
#pragma unroll
        for (int k = 0; k < 32; ++k) h[k] = hS[tid * 33 + k];
        const float inv32 = 0.17677669529663687f;  // 1/sqrt(32)
        float o = b4S[0];
#pragma unroll 4
        for (int w = 0; w < 32; ++w) {
            float z = 0.0f;
#pragma unroll
            for (int k = 0; k < 32; ++k) z += h[k] * w3S[k * 32 + w];
            z = z * inv32 + b3S[w];
            o += silu_f(z) * (w4S[w] * inv32);
        }
        out[nb + tid] = o;
    }
}

// ============================================================================
extern "C" void kernel_launch(void* const* d_in, const int* in_sizes, int n_in,
                              void* d_out, int out_size) {
    const float* node_vec = (const float*)d_in[0];
    const float* attr     = (const float*)d_in[1];
    const float* W1s      = (const float*)d_in[2];
    const float* b1s      = (const float*)d_in[3];
    // d_in[4..7] = W1g, b1g, W1v1, W1v2 : dead in the reference
    const float* W2       = (const float*)d_in[8];
    const float* b2       = (const float*)d_in[9];
    const float* W3       = (const float*)d_in[10];
    const float* b3       = (const float*)d_in[11];
    const float* W4       = (const float*)d_in[12];
    const float* b4       = (const float*)d_in[13];
    float* out = (float*)d_out;

    const int N = out_size;                    // 8192

    dim3 g1(64, 2);
    prep_w1<<<g1, 256>>>(W1s);
    prep_w2<<<64, 256>>>(W2);

    cudaFuncSetAttribute(eq_hmma, cudaFuncAttributeMaxDynamicSharedMemorySize,
                         (int)SMEM_BYTES);
    eq_hmma<<<N / MT, THREADS, SMEM_BYTES>>>(node_vec, attr, b1s, b2, W3, b3, W4, b4, out);
}

// round 5
// speedup vs baseline: 2.3533x; 1.0390x over previous
#include <cuda_runtime.h>
#include <cuda_fp16.h>
#include <cstdint>

// ============================================================================
// Problem constants
// ============================================================================
#define NU 128         // MUL0
#define NV 32          // A
#define KTOT 4096      // NU*NV
#define MT 64          // nodes per block
#define NCHUNK 64      // KTOT/64
#define THREADS 512    // 8 consumer warps + 8 producer warps
#define PT 256         // producer thread count

// pre-transposed / hi-lo split weights (scale 1/8 folded in; A side gets 1/8 too)
__device__ __align__(16) __half g_W1T_hi[NU * KTOT];
__device__ __align__(16) __half g_W1T_lo[NU * KTOT];
__device__ __align__(16) __half g_W2T_hi[NV * KTOT];
__device__ __align__(16) __half g_W2T_lo[NV * KTOT];

// ---- smem layout (bytes) ----
constexpr uint32_t OFF_A    = 0;          // A tiles: [buf][hi/lo] 4 x 8192  = 32768
constexpr uint32_t OFF_B    = 32768;      // B tiles: [buf][hi/lo] 4 x 16384 = 65536
constexpr uint32_t OFF_S    = 98304;      // sT / aT fp32 [128u][65]  = 33280
constexpr uint32_t OFF_ATTR = 131584;     // attr fp32 [64n][36]      = 9216
constexpr uint32_t OFF_H    = 140800;     // h fp32 [64n][33]         = 8448
constexpr uint32_t OFF_W3   = 149248;     // 4096
constexpr uint32_t OFF_B1   = 153344;     // 512
constexpr uint32_t OFF_B2   = 153856;     // 128
constexpr uint32_t OFF_B3   = 153984;     // 128
constexpr uint32_t OFF_W4   = 154112;     // 128
constexpr uint32_t OFF_B4   = 154240;     // 16
constexpr uint32_t SMEM_BYTES = 154368;   // ~150.8 KB

extern __shared__ char smem_raw[];

__device__ __forceinline__ uint32_t smem_u32(const void* p) {
    uint32_t a;
    asm("{ .reg .u64 t; cvta.to.shared.u64 t, %1; cvt.u32.u64 %0, t; }" : "=r"(a) : "l"(p));
    return a;
}
__device__ __forceinline__ uint32_t swz(uint32_t o) { return o ^ ((o >> 3) & 0x70); }
__device__ __forceinline__ float silu_f(float x) { return x / (1.0f + __expf(-x)); }

#define STS128(r0, r1, r2, r3, sa) \
    asm volatile("st.shared.v4.b32 [%0], {%1, %2, %3, %4};" \
                 :: "r"(sa), "r"(r0), "r"(r1), "r"(r2), "r"(r3) : "memory")

__device__ __forceinline__ void ldsm4(uint32_t* r, uint32_t addr) {
    asm volatile("ldmatrix.sync.aligned.m8n8.x4.shared.b16 {%0,%1,%2,%3}, [%4];"
                 : "=r"(r[0]), "=r"(r[1]), "=r"(r[2]), "=r"(r[3]) : "r"(addr));
}
// main pass: fp16 operands, fp32 accumulators
__device__ __forceinline__ void mma_f32(float* c, const uint32_t* a,
                                        uint32_t b0, uint32_t b1) {
    asm volatile(
        "mma.sync.aligned.m16n8k16.row.col.f32.f16.f16.f32 "
        "{%0,%1,%2,%3}, {%4,%5,%6,%7}, {%8,%9}, {%0,%1,%2,%3};"
        : "+f"(c[0]), "+f"(c[1]), "+f"(c[2]), "+f"(c[3])
        : "r"(a[0]), "r"(a[1]), "r"(a[2]), "r"(a[3]), "r"(b0), "r"(b1));
}
// correction passes: fp16 operands, fp16 accumulators (2x rate)
__device__ __forceinline__ void mma_f16(uint32_t* c, const uint32_t* a,
                                        uint32_t b0, uint32_t b1) {
    asm volatile(
        "mma.sync.aligned.m16n8k16.row.col.f16.f16.f16.f16 "
        "{%0,%1}, {%2,%3,%4,%5}, {%6,%7}, {%0,%1};"
        : "+r"(c[0]), "+r"(c[1])
        : "r"(a[0]), "r"(a[1]), "r"(a[2]), "r"(a[3]), "r"(b0), "r"(b1));
}

// ============================================================================
// merged prep kernel: W[k][w] fp32 -> W^T[w][k] fp16 hi/lo, 1/8 scale folded
// blocks [0,256): W1 (32k x 64w tiles); blocks [256,320): W2 (64k x 32w tiles)
// ============================================================================
__global__ void __launch_bounds__(256) prep_all(const float* __restrict__ W1s,
                                                const float* __restrict__ W2) {
    __shared__ float tile[64][65];
    const int t = threadIdx.x;
    const int b = blockIdx.x;
    if (b < 256) {
        const int k0 = (b & 127) * 32;
        const int w0 = (b >> 7) * 64;
#pragma unroll
        for (int it = 0; it < 2; ++it) {           // 512 float4 slots
            int s = it * 256 + t;
            int r = s >> 4, q = s & 15;
            float4 v = *(const float4*)(W1s + (size_t)(k0 + r) * NU + w0 + q * 4);
            tile[r][q * 4 + 0] = v.x; tile[r][q * 4 + 1] = v.y;
            tile[r][q * 4 + 2] = v.z; tile[r][q * 4 + 3] = v.w;
        }
        __syncthreads();
        const int w = t >> 2, kq = t & 3;          // 64 w x 4 uint4 (32 k)
        uint32_t hb[4], lb[4];
#pragma unroll
        for (int q = 0; q < 4; ++q) {
            float x0 = tile[kq * 8 + 2 * q][w]     * 0.125f;
            float x1 = tile[kq * 8 + 2 * q + 1][w] * 0.125f;
            __half h0 = __float2half_rn(x0), h1 = __float2half_rn(x1);
            float r0 = x0 - __half2float(h0), r1 = x1 - __half2float(h1);
            __half l0 = __float2half_rn(r0), l1 = __float2half_rn(r1);
            hb[q] = (uint32_t)__half_as_ushort(h0) | ((uint32_t)__half_as_ushort(h1) << 16);
            lb[q] = (uint32_t)__half_as_ushort(l0) | ((uint32_t)__half_as_ushort(l1) << 16);
        }
        ((uint4*)(g_W1T_hi + (size_t)(w0 + w) * KTOT + k0))[kq] =
            make_uint4(hb[0], hb[1], hb[2], hb[3]);
        ((uint4*)(g_W1T_lo + (size_t)(w0 + w) * KTOT + k0))[kq] =
            make_uint4(lb[0], lb[1], lb[2], lb[3]);
    } else {
        const int k0 = (b - 256) * 64;
#pragma unroll
        for (int it = 0; it < 2; ++it) {           // 512 float4 slots
            int s = it * 256 + t;
            int r = s >> 3, q = s & 7;
            float4 v = *(const float4*)(W2 + (size_t)(k0 + r) * NV + q * 4);
            tile[r][q * 4 + 0] = v.x; tile[r][q * 4 + 1] = v.y;
            tile[r][q * 4 + 2] = v.z; tile[r][q * 4 + 3] = v.w;
        }
        __syncthreads();
        const int w = t >> 3, kq = t & 7;          // 32 w x 8 uint4 (64 k)
        uint32_t hb[4], lb[4];
#pragma unroll
        for (int q = 0; q < 4; ++q) {
            float x0 = tile[kq * 8 + 2 * q][w]     * 0.125f;
            float x1 = tile[kq * 8 + 2 * q + 1][w] * 0.125f;
            __half h0 = __float2half_rn(x0), h1 = __float2half_rn(x1);
            float r0 = x0 - __half2float(h0), r1 = x1 - __half2float(h1);
            __half l0 = __float2half_rn(r0), l1 = __float2half_rn(r1);
            hb[q] = (uint32_t)__half_as_ushort(h0) | ((uint32_t)__half_as_ushort(h1) << 16);
            lb[q] = (uint32_t)__half_as_ushort(l0) | ((uint32_t)__half_as_ushort(l1) << 16);
        }
        ((uint4*)(g_W2T_hi + (size_t)w * KTOT + k0))[kq] =
            make_uint4(hb[0], hb[1], hb[2], hb[3]);
        ((uint4*)(g_W2T_lo + (size_t)w * KTOT + k0))[kq] =
            make_uint4(lb[0], lb[1], lb[2], lb[3]);
    }
}

// ============================================================================
// tile fills (producer warps, ptid in [0,256))
// ============================================================================
__device__ __forceinline__ void fillA(int c, uint32_t aH, uint32_t aL,
                                      const float* srcT, const float* attrS, int ptid) {
#pragma unroll
    for (int j = 0; j < 2; ++j) {
        int slot = ptid + j * PT;            // 0..511
        int n = slot >> 3, kg = slot & 7;
        int u = (c << 1) + (kg >> 2);
        int vb = (kg & 3) << 3;
        float su = srcT[u * 65 + n] * 0.125f;      // A-side scale
        float4 a0 = *(const float4*)(attrS + n * 36 + vb);
        float4 a1 = *(const float4*)(attrS + n * 36 + vb + 4);
        float v[8] = {a0.x, a0.y, a0.z, a0.w, a1.x, a1.y, a1.z, a1.w};
        uint32_t hb[4], lb[4];
#pragma unroll
        for (int q = 0; q < 4; ++q) {
            float x0 = su * v[2 * q], x1 = su * v[2 * q + 1];
            __half h0 = __float2half_rn(x0), h1 = __float2half_rn(x1);
            float r0 = x0 - __half2float(h0), r1 = x1 - __half2float(h1);
            __half l0 = __float2half_rn(r0), l1 = __float2half_rn(r1);
            hb[q] = (uint32_t)__half_as_ushort(h0) | ((uint32_t)__half_as_ushort(h1) << 16);
            lb[q] = (uint32_t)__half_as_ushort(l0) | ((uint32_t)__half_as_ushort(l1) << 16);
        }
        uint32_t sw = swz((uint32_t)(n * 128 + (kg << 4)));
        STS128(hb[0], hb[1], hb[2], hb[3], aH + sw);
        STS128(lb[0], lb[1], lb[2], lb[3], aL + sw);
    }
}

template <int BROWS>
__device__ __forceinline__ void fillB(int c, uint32_t bH, uint32_t bL,
                                      const __half* gHi, const __half* gLo, int ptid) {
#pragma unroll
    for (int j = 0; j < (BROWS * 16) / PT; ++j) {
        int slot = ptid + j * PT;            // [0, BROWS*16)
        int hl = (slot >= BROWS * 8) ? 1 : 0;
        int s2 = slot - hl * BROWS * 8;
        int row = s2 >> 3, kg = s2 & 7;
        uint4 val = ((const uint4*)(hl ? gLo : gHi))[row * 512 + c * 8 + kg];
        uint32_t sw = swz((uint32_t)(row * 128 + (kg << 4)));
        STS128(val.x, val.y, val.z, val.w, (hl ? bL : bH) + sw);
    }
}

// ============================================================================
// main fused kernel: one block = 64 nodes; warps 0-7 MMA, warps 8-15 fill
// ============================================================================
__global__ void __launch_bounds__(THREADS, 1)
eq_hmma(const float* __restrict__ node_vec,   // [N,480]
        const float* __restrict__ attr_g,     // [N,32]
        const float* __restrict__ b1s,        // [128]
        const float* __restrict__ b2,         // [32]
        const float* __restrict__ W3,         // [32,32]
        const float* __restrict__ b3,         // [32]
        const float* __restrict__ W4,         // [32]
        const float* __restrict__ b4,         // [1]
        float* __restrict__ out)              // [N]
{
    const int tid  = threadIdx.x;
    const int wid  = tid >> 5;
    const int lane = tid & 31;
    const int nb   = blockIdx.x * MT;
    const uint32_t sb = smem_u32(smem_raw);
    const bool producer = (wid >= 8);
    const int ptid = tid - 256;

    float* sT    = (float*)(smem_raw + OFF_S);     // [u][65]
    float* attrS = (float*)(smem_raw + OFF_ATTR);  // [n][36]
    float* hS    = (float*)(smem_raw + OFF_H);     // [n][33]
    float* w3S   = (float*)(smem_raw + OFF_W3);
    float* b1S   = (float*)(smem_raw + OFF_B1);
    float* b2S   = (float*)(smem_raw + OFF_B2);
    float* b3S   = (float*)(smem_raw + OFF_B3);
    float* w4S   = (float*)(smem_raw + OFF_W4);
    float* b4S   = (float*)(smem_raw + OFF_B4);

    // ---- load block inputs (all 512 threads) ----
#pragma unroll
    for (int j = 0; j < 4; ++j) {              // s -> transposed [u][65]
        int i = tid + j * THREADS;             // 2048 float4 slots
        int n = i >> 5, c4 = i & 31;
        float4 v = *(const float4*)(node_vec + (size_t)(nb + n) * 480 + c4 * 4);
        sT[(c4 * 4 + 0) * 65 + n] = v.x;
        sT[(c4 * 4 + 1) * 65 + n] = v.y;
        sT[(c4 * 4 + 2) * 65 + n] = v.z;
        sT[(c4 * 4 + 3) * 65 + n] = v.w;
    }
    {                                          // attr -> [n][36] (512 float4 slots)
        int n = tid >> 3, c4 = tid & 7;
        *(float4*)(attrS + n * 36 + c4 * 4) =
            *(const float4*)(attr_g + (size_t)(nb + n) * NV + c4 * 4);
    }
    if (tid < 256) ((float4*)w3S)[tid] = ((const float4*)W3)[tid];
    if (tid < 128) b1S[tid] = b1s[tid];
    if (tid < 32) { b2S[tid] = b2[tid]; b3S[tid] = b3[tid]; w4S[tid] = W4[tid]; }
    if (tid == 0) b4S[0] = b4[0];
    __syncthreads();

    // ldmatrix per-lane offsets
    const uint32_t rowA = (uint32_t)((((lane >> 3) & 1) << 3) + (lane & 7));
    const uint32_t colA = (uint32_t)((lane >> 4) << 4);
    const uint32_t rowB = (uint32_t)(((lane >> 4) << 3) + (lane & 7));
    const uint32_t colB = (uint32_t)(((lane >> 3) & 1) << 4);

    auto tA = [&](int buf, int h) { return sb + OFF_A + (uint32_t)((buf * 2 + h) * 8192); };
    auto tB = [&](int buf, int h) { return sb + OFF_B + (uint32_t)((buf * 2 + h) * 16384); };

    // ======================= stage 1: C[64,128], K=4096 =======================
    {
        const int m0 = (wid >> 2) * 32;        // consumers only (wid<8)
        const int n0 = (wid & 3) * 32;
        float    accF[2][4][4];
        uint32_t accC[2][4][2];
#pragma unroll
        for (int a = 0; a < 2; ++a)
#pragma unroll
            for (int b = 0; b < 4; ++b) {
#pragma unroll
                for (int q = 0; q < 4; ++q) accF[a][b][q] = 0.0f;
                accC[a][b][0] = 0u; accC[a][b][1] = 0u;
            }

        if (producer) {
            fillA(0, tA(0, 0), tA(0, 1), sT, attrS, ptid);
            fillB<128>(0, tB(0, 0), tB(0, 1), g_W1T_hi, g_W1T_lo, ptid);
        }
        __syncthreads();

        for (int c = 0; c < NCHUNK; ++c) {
            const int cb = c & 1;
            if (producer) {
                if (c + 1 < NCHUNK) {
                    fillA(c + 1, tA(cb ^ 1, 0), tA(cb ^ 1, 1), sT, attrS, ptid);
                    fillB<128>(c + 1, tB(cb ^ 1, 0), tB(cb ^ 1, 1), g_W1T_hi, g_W1T_lo, ptid);
                }
            } else {
                const uint32_t aHb = tA(cb, 0), aLb = tA(cb, 1);
                const uint32_t bHb = tB(cb, 0), bLb = tB(cb, 1);
#pragma unroll
                for (int ks = 0; ks < 4; ++ks) {
                    uint32_t aH[2][4], aL[2][4], bH[2][4], bL[2][4];
#pragma unroll
                    for (int mf = 0; mf < 2; ++mf) {
                        uint32_t off = swz((uint32_t)((m0 + mf * 16 + rowA) * 128 + ks * 32 + colA));
                        ldsm4(aH[mf], aHb + off);
                        ldsm4(aL[mf], aLb + off);
                    }
#pragma unroll
                    for (int nbk = 0; nbk < 2; ++nbk) {
                        uint32_t off = swz((uint32_t)((n0 + nbk * 16 + rowB) * 128 + ks * 32 + colB));
                        ldsm4(bH[nbk], bHb + off);
                        ldsm4(bL[nbk], bLb + off);
                    }
#pragma unroll
                    for (int mf = 0; mf < 2; ++mf)
#pragma unroll
                        for (int nf = 0; nf < 4; ++nf) {
                            uint32_t h0 = bH[nf >> 1][(nf & 1) * 2], h1 = bH[nf >> 1][(nf & 1) * 2 + 1];
                            uint32_t l0 = bL[nf >> 1][(nf & 1) * 2], l1 = bL[nf >> 1][(nf & 1) * 2 + 1];
                            mma_f32(accF[mf][nf], aH[mf], h0, h1);
                            mma_f16(accC[mf][nf], aH[mf], l0, l1);
                            mma_f16(accC[mf][nf], aL[mf], h0, h1);
                        }
                }
            }
            __syncthreads();
        }

        // epilogue 1: silu(c + corr + b1) -> sT[w][node] (consumers)
        if (!producer) {
#pragma unroll
            for (int mf = 0; mf < 2; ++mf)
#pragma unroll
                for (int nf = 0; nf < 4; ++nf) {
                    int m = m0 + mf * 16 + (lane >> 2);
                    int w = n0 + nf * 8 + ((lane & 3) << 1);
                    float* cc = accF[mf][nf];
                    float2 p0 = __half22float2(*(__half2*)&accC[mf][nf][0]);
                    float2 p1 = __half22float2(*(__half2*)&accC[mf][nf][1]);
                    sT[w * 65 + m]           = silu_f(cc[0] + p0.x + b1S[w]);
                    sT[(w + 1) * 65 + m]     = silu_f(cc[1] + p0.y + b1S[w + 1]);
                    sT[w * 65 + m + 8]       = silu_f(cc[2] + p1.x + b1S[w]);
                    sT[(w + 1) * 65 + m + 8] = silu_f(cc[3] + p1.y + b1S[w + 1]);
                }
        }
        __syncthreads();
    }

    // ======================= stage 2: C[64,32], K=4096 =======================
    {
        const int m0 = (wid >> 1) * 16;
        const int n0 = (wid & 1) * 16;
        float    accF[2][4];
        uint32_t accC[2][2];
#pragma unroll
        for (int b = 0; b < 2; ++b) {
#pragma unroll
            for (int q = 0; q < 4; ++q) accF[b][q] = 0.0f;
            accC[b][0] = 0u; accC[b][1] = 0u;
        }

        if (producer) {
            fillA(0, tA(0, 0), tA(0, 1), sT, attrS, ptid);
            fillB<32>(0, tB(0, 0), tB(0, 1), g_W2T_hi, g_W2T_lo, ptid);
        }
        __syncthreads();

        for (int c = 0; c < NCHUNK; ++c) {
            const int cb = c & 1;
            if (producer) {
                if (c + 1 < NCHUNK) {
                    fillA(c + 1, tA(cb ^ 1, 0), tA(cb ^ 1, 1), sT, attrS, ptid);
                    fillB<32>(c + 1, tB(cb ^ 1, 0), tB(cb ^ 1, 1), g_W2T_hi, g_W2T_lo, ptid);
                }
            } else {
                const uint32_t aHb = tA(cb, 0), aLb = tA(cb, 1);
                const uint32_t bHb = tB(cb, 0), bLb = tB(cb, 1);
#pragma unroll
                for (int ks = 0; ks < 4; ++ks) {
                    uint32_t aH[4], aL[4], bH[4], bL[4];
                    {
                        uint32_t off = swz((uint32_t)((m0 + rowA) * 128 + ks * 32 + colA));
                        ldsm4(aH, aHb + off);
                        ldsm4(aL, aLb + off);
                    }
                    {
                        uint32_t off = swz((uint32_t)((n0 + rowB) * 128 + ks * 32 + colB));
                        ldsm4(bH, bHb + off);
                        ldsm4(bL, bLb + off);
                    }
#pragma unroll
                    for (int nf = 0; nf < 2; ++nf) {
                        uint32_t h0 = bH[nf * 2], h1 = bH[nf * 2 + 1];
                        uint32_t l0 = bL[nf * 2], l1 = bL[nf * 2 + 1];
                        mma_f32(accF[nf], aH, h0, h1);
                        mma_f16(accC[nf], aH, l0, l1);
                        mma_f16(accC[nf], aL, h0, h1);
                    }
                }
            }
            __syncthreads();
        }

        // epilogue 2: h = c + corr + b2 -> hS[node][33]
        if (!producer) {
#pragma unroll
            for (int nf = 0; nf < 2; ++nf) {
                int m = m0 + (lane >> 2);
                int w = n0 + nf * 8 + ((lane & 3) << 1);
                float* cc = accF[nf];
                float2 p0 = __half22float2(*(__half2*)&accC[nf][0]);
                float2 p1 = __half22float2(*(__half2*)&accC[nf][1]);
                hS[m * 33 + w]           = cc[0] + p0.x + b2S[w];
                hS[m * 33 + w + 1]       = cc[1] + p0.y + b2S[w + 1];
                hS[(m + 8) * 33 + w]     = cc[2] + p1.x + b2S[w];
                hS[(m + 8) * 33 + w + 1] = cc[3] + p1.y + b2S[w + 1];
            }
        }
        __syncthreads();
    }

    // ======================= stage 3/4: 8 threads per node =======================
    {
        const int node  = tid >> 3;
        const int lane8 = tid & 7;
        const float inv32 = 0.17677669529663687f;  // 1/sqrt(32)
        float o = 0.0f;
#pragma unroll
        for (int j = 0; j < 4; ++j) {
            int w = lane8 + j * 8;
            float z = 0.0f;
#pragma unroll
            for (int k = 0; k < 32; ++k) z += hS[node * 33 + k] * w3S[k * 32 + w];
            z = z * inv32 + b3S[w];
            o += silu_f(z) * (w4S[w] * inv32);
        }
#pragma unroll
        for (int m = 1; m < 8; m <<= 1)
            o += __shfl_xor_sync(0xffffffff, o, m);
        if (lane8 == 0) out[nb + node] = o + b4S[0];
    }
}

// ============================================================================
extern "C" void kernel_launch(void* const* d_in, const int* in_sizes, int n_in,
                              void* d_out, int out_size) {
    const float* node_vec = (const float*)d_in[0];
    const float* attr     = (const float*)d_in[1];
    const float* W1s      = (const float*)d_in[2];
    const float* b1s      = (const float*)d_in[3];
    // d_in[4..7] = W1g, b1g, W1v1, W1v2 : dead in the reference
    const float* W2       = (const float*)d_in[8];
    const float* b2       = (const float*)d_in[9];
    const float* W3       = (const float*)d_in[10];
    const float* b3       = (const float*)d_in[11];
    const float* W4       = (const float*)d_in[12];
    const float* b4       = (const float*)d_in[13];
    float* out = (float*)d_out;

    const int N = out_size;                    // 8192

    prep_all<<<320, 256>>>(W1s, W2);

    cudaFuncSetAttribute(eq_hmma, cudaFuncAttributeMaxDynamicSharedMemorySize,
                         (int)SMEM_BYTES);
    eq_hmma<<<N / MT, THREADS, SMEM_BYTES>>>(node_vec, attr, b1s, b2, W3, b3, W4, b4, out);
}

// round 6
// speedup vs baseline: 2.4112x; 1.0246x over previous
#include <cuda_runtime.h>
#include <cuda_fp16.h>
#include <cstdint>

// ============================================================================
// Problem constants
// ============================================================================
#define NU 128         // MUL0
#define NV 32          // A
#define KTOT 4096      // NU*NV
#define MT 64          // nodes per block
#define NCHUNK 64      // KTOT/64 per stage
#define THREADS 512    // 8 consumer warps + 8 producer warps
#define PT 256         // producer thread count
#define DEPTH 3        // pipeline buffers

// pre-transposed / hi-lo split weights (scale 1/8 folded in; A side gets 1/8 too)
__device__ __align__(16) __half g_W1T_hi[NU * KTOT];
__device__ __align__(16) __half g_W1T_lo[NU * KTOT];
__device__ __align__(16) __half g_W2T_hi[NV * KTOT];
__device__ __align__(16) __half g_W2T_lo[NV * KTOT];

// ---- smem layout (bytes) ----
// [0,48): 6 mbarriers (full0..2 @0/8/16, empty0..2 @24/32/40)
constexpr uint32_t OFF_A    = 1024;       // 3 bufs x (hi 8KB + lo 8KB) = 49152
constexpr uint32_t OFF_B    = 50176;      // 3 bufs x (hi 16KB + lo 16KB) = 98304
constexpr uint32_t OFF_S    = 148480;     // sT / aT fp32 [128u][65] = 33280
constexpr uint32_t OFF_ATTR = 181760;     // attr fp32 [64n][36] = 9216
constexpr uint32_t OFF_H    = 190976;     // h fp32 [64n][33] = 8448
constexpr uint32_t OFF_W3   = 199424;     // 4096
constexpr uint32_t OFF_B1   = 203520;     // 512
constexpr uint32_t OFF_B2   = 204032;     // 128
constexpr uint32_t OFF_B3   = 204160;     // 128
constexpr uint32_t OFF_W4   = 204288;     // 128
constexpr uint32_t OFF_B4   = 204416;     // 16
constexpr uint32_t SMEM_BYTES = 204432;   // ~199.6 KB

extern __shared__ char smem_raw[];

__device__ __forceinline__ uint32_t smem_u32(const void* p) {
    uint32_t a;
    asm("{ .reg .u64 t; cvta.to.shared.u64 t, %1; cvt.u32.u64 %0, t; }" : "=r"(a) : "l"(p));
    return a;
}
__device__ __forceinline__ uint32_t swz(uint32_t o) { return o ^ ((o >> 3) & 0x70); }
__device__ __forceinline__ float silu_f(float x) { return x / (1.0f + __expf(-x)); }

#define STS128(r0, r1, r2, r3, sa) \
    asm volatile("st.shared.v4.b32 [%0], {%1, %2, %3, %4};" \
                 :: "r"(sa), "r"(r0), "r"(r1), "r"(r2), "r"(r3) : "memory")

// block-wide named barrier usable inside divergent producer/consumer paths
#define BARX() asm volatile("bar.sync 15, %0;" :: "n"(THREADS) : "memory")

#define MBARRIER_INIT(mb, cnt) \
    asm volatile("mbarrier.init.shared.b64 [%0], %1;" :: "r"((uint32_t)(mb)), "r"((uint32_t)(cnt)) : "memory")
#define MBARRIER_ARRIVE(mb) \
    asm volatile("mbarrier.arrive.shared.b64 _, [%0];" :: "r"((uint32_t)(mb)) : "memory")
#define MBARRIER_WAIT_PARITY(mb, par) do { \
    uint32_t _mb = (uint32_t)(mb); uint32_t _p = (uint32_t)(par); uint32_t _done; \
    asm volatile("{\n\t.reg .pred p;\n\t" \
        "mbarrier.try_wait.parity.acquire.cta.shared::cta.b64 p, [%1], %2;\n\t" \
        "selp.b32 %0, 1, 0, p;\n\t}" : "=r"(_done) : "r"(_mb), "r"(_p) : "memory"); \
    if (!_done) { \
        asm volatile("{\n\t.reg .pred P1;\n\t" \
            "WL_%=:\n\t" \
            "mbarrier.try_wait.parity.acquire.cta.shared::cta.b64 P1, [%0], %1, 0x989680;\n\t" \
            "@P1 bra.uni WD_%=;\n\tbra.uni WL_%=;\n\tWD_%=:\n\t}" \
            :: "r"(_mb), "r"(_p) : "memory"); \
    } } while(0)

__device__ __forceinline__ void ldsm4(uint32_t* r, uint32_t addr) {
    asm volatile("ldmatrix.sync.aligned.m8n8.x4.shared.b16 {%0,%1,%2,%3}, [%4];"
                 : "=r"(r[0]), "=r"(r[1]), "=r"(r[2]), "=r"(r[3]) : "r"(addr));
}
// main pass: fp16 operands, fp32 accumulators
__device__ __forceinline__ void mma_f32(float* c, const uint32_t* a,
                                        uint32_t b0, uint32_t b1) {
    asm volatile(
        "mma.sync.aligned.m16n8k16.row.col.f32.f16.f16.f32 "
        "{%0,%1,%2,%3}, {%4,%5,%6,%7}, {%8,%9}, {%0,%1,%2,%3};"
        : "+f"(c[0]), "+f"(c[1]), "+f"(c[2]), "+f"(c[3])
        : "r"(a[0]), "r"(a[1]), "r"(a[2]), "r"(a[3]), "r"(b0), "r"(b1));
}
// correction passes: fp16 operands, fp16 accumulators
__device__ __forceinline__ void mma_f16(uint32_t* c, const uint32_t* a,
                                        uint32_t b0, uint32_t b1) {
    asm volatile(
        "mma.sync.aligned.m16n8k16.row.col.f16.f16.f16.f16 "
        "{%0,%1}, {%2,%3,%4,%5}, {%6,%7}, {%0,%1};"
        : "+r"(c[0]), "+r"(c[1])
        : "r"(a[0]), "r"(a[1]), "r"(a[2]), "r"(a[3]), "r"(b0), "r"(b1));
}

// ============================================================================
// merged prep kernel: W[k][w] fp32 -> W^T[w][k] fp16 hi/lo, 1/8 scale folded
// ============================================================================
__global__ void __launch_bounds__(256) prep_all(const float* __restrict__ W1s,
                                                const float* __restrict__ W2) {
    __shared__ float tile[64][65];
    const int t = threadIdx.x;
    const int b = blockIdx.x;
    if (b < 256) {
        const int k0 = (b & 127) * 32;
        const int w0 = (b >> 7) * 64;
#pragma unroll
        for (int it = 0; it < 2; ++it) {
            int s = it * 256 + t;
            int r = s >> 4, q = s & 15;
            float4 v = *(const float4*)(W1s + (size_t)(k0 + r) * NU + w0 + q * 4);
            tile[r][q * 4 + 0] = v.x; tile[r][q * 4 + 1] = v.y;
            tile[r][q * 4 + 2] = v.z; tile[r][q * 4 + 3] = v.w;
        }
        __syncthreads();
        const int w = t >> 2, kq = t & 3;
        uint32_t hb[4], lb[4];
#pragma unroll
        for (int q = 0; q < 4; ++q) {
            float x0 = tile[kq * 8 + 2 * q][w]     * 0.125f;
            float x1 = tile[kq * 8 + 2 * q + 1][w] * 0.125f;
            __half h0 = __float2half_rn(x0), h1 = __float2half_rn(x1);
            float r0 = x0 - __half2float(h0), r1 = x1 - __half2float(h1);
            __half l0 = __float2half_rn(r0), l1 = __float2half_rn(r1);
            hb[q] = (uint32_t)__half_as_ushort(h0) | ((uint32_t)__half_as_ushort(h1) << 16);
            lb[q] = (uint32_t)__half_as_ushort(l0) | ((uint32_t)__half_as_ushort(l1) << 16);
        }
        ((uint4*)(g_W1T_hi + (size_t)(w0 + w) * KTOT + k0))[kq] =
            make_uint4(hb[0], hb[1], hb[2], hb[3]);
        ((uint4*)(g_W1T_lo + (size_t)(w0 + w) * KTOT + k0))[kq] =
            make_uint4(lb[0], lb[1], lb[2], lb[3]);
    } else {
        const int k0 = (b - 256) * 64;
#pragma unroll
        for (int it = 0; it < 2; ++it) {
            int s = it * 256 + t;
            int r = s >> 3, q = s & 7;
            float4 v = *(const float4*)(W2 + (size_t)(k0 + r) * NV + q * 4);
            tile[r][q * 4 + 0] = v.x; tile[r][q * 4 + 1] = v.y;
            tile[r][q * 4 + 2] = v.z; tile[r][q * 4 + 3] = v.w;
        }
        __syncthreads();
        const int w = t >> 3, kq = t & 7;
        uint32_t hb[4], lb[4];
#pragma unroll
        for (int q = 0; q < 4; ++q) {
            float x0 = tile[kq * 8 + 2 * q][w]     * 0.125f;
            float x1 = tile[kq * 8 + 2 * q + 1][w] * 0.125f;
            __half h0 = __float2half_rn(x0), h1 = __float2half_rn(x1);
            float r0 = x0 - __half2float(h0), r1 = x1 - __half2float(h1);
            __half l0 = __float2half_rn(r0), l1 = __float2half_rn(r1);
            hb[q] = (uint32_t)__half_as_ushort(h0) | ((uint32_t)__half_as_ushort(h1) << 16);
            lb[q] = (uint32_t)__half_as_ushort(l0) | ((uint32_t)__half_as_ushort(l1) << 16);
        }
        ((uint4*)(g_W2T_hi + (size_t)w * KTOT + k0))[kq] =
            make_uint4(hb[0], hb[1], hb[2], hb[3]);
        ((uint4*)(g_W2T_lo + (size_t)w * KTOT + k0))[kq] =
            make_uint4(lb[0], lb[1], lb[2], lb[3]);
    }
}

// ============================================================================
// tile fills (producer warps, ptid in [0,256))
// ============================================================================
__device__ __forceinline__ void fillA(int c, uint32_t aH, uint32_t aL,
                                      const float* srcT, const float* attrS, int ptid) {
#pragma unroll
    for (int j = 0; j < 2; ++j) {
        int slot = ptid + j * PT;            // 0..511
        int n = slot >> 3, kg = slot & 7;
        int u = (c << 1) + (kg >> 2);
        int vb = (kg & 3) << 3;
        float su = srcT[u * 65 + n] * 0.125f;      // A-side scale
        float4 a0 = *(const float4*)(attrS + n * 36 + vb);
        float4 a1 = *(const float4*)(attrS + n * 36 + vb + 4);
        float v[8] = {a0.x, a0.y, a0.z, a0.w, a1.x, a1.y, a1.z, a1.w};
        uint32_t hb[4], lb[4];
#pragma unroll
        for (int q = 0; q < 4; ++q) {
            float x0 = su * v[2 * q], x1 = su * v[2 * q + 1];
            __half h0 = __float2half_rn(x0), h1 = __float2half_rn(x1);
            float r0 = x0 - __half2float(h0), r1 = x1 - __half2float(h1);
            __half l0 = __float2half_rn(r0), l1 = __float2half_rn(r1);
            hb[q] = (uint32_t)__half_as_ushort(h0) | ((uint32_t)__half_as_ushort(h1) << 16);
            lb[q] = (uint32_t)__half_as_ushort(l0) | ((uint32_t)__half_as_ushort(l1) << 16);
        }
        uint32_t sw = swz((uint32_t)(n * 128 + (kg << 4)));
        STS128(hb[0], hb[1], hb[2], hb[3], aH + sw);
        STS128(lb[0], lb[1], lb[2], lb[3], aL + sw);
    }
}

template <int BROWS>
__device__ __forceinline__ void fillB(int c, uint32_t bH, uint32_t bL,
                                      const __half* gHi, const __half* gLo, int ptid) {
#pragma unroll
    for (int j = 0; j < (BROWS * 16) / PT; ++j) {
        int slot = ptid + j * PT;            // [0, BROWS*16)
        int hl = (slot >= BROWS * 8) ? 1 : 0;
        int s2 = slot - hl * BROWS * 8;
        int row = s2 >> 3, kg = s2 & 7;
        uint4 val = ((const uint4*)(hl ? gLo : gHi))[row * 512 + c * 8 + kg];
        uint32_t sw = swz((uint32_t)(row * 128 + (kg << 4)));
        STS128(val.x, val.y, val.z, val.w, (hl ? bL : bH) + sw);
    }
}

// ============================================================================
// main fused kernel: one block = 64 nodes; warps 0-7 MMA, warps 8-15 fill
// 3-deep mbarrier pipeline, global chunk index g in [0,128)
// ============================================================================
__global__ void __launch_bounds__(THREADS, 1)
eq_hmma(const float* __restrict__ node_vec,   // [N,480]
        const float* __restrict__ attr_g,     // [N,32]
        const float* __restrict__ b1s,        // [128]
        const float* __restrict__ b2,         // [32]
        const float* __restrict__ W3,         // [32,32]
        const float* __restrict__ b3,         // [32]
        const float* __restrict__ W4,         // [32]
        const float* __restrict__ b4,         // [1]
        float* __restrict__ out)              // [N]
{
    const int tid  = threadIdx.x;
    const int wid  = tid >> 5;
    const int lane = tid & 31;
    const int nb   = blockIdx.x * MT;
    const uint32_t sb = smem_u32(smem_raw);
    const bool producer = (wid >= 8);
    const int ptid = tid - 256;

    float* sT    = (float*)(smem_raw + OFF_S);     // [u][65]
    float* attrS = (float*)(smem_raw + OFF_ATTR);  // [n][36]
    float* hS    = (float*)(smem_raw + OFF_H);     // [n][33]
    float* w3S   = (float*)(smem_raw + OFF_W3);
    float* b1S   = (float*)(smem_raw + OFF_B1);
    float* b2S   = (float*)(smem_raw + OFF_B2);
    float* b3S   = (float*)(smem_raw + OFF_B3);
    float* w4S   = (float*)(smem_raw + OFF_W4);
    float* b4S   = (float*)(smem_raw + OFF_B4);

    auto mbF = [&](int b) { return sb + (uint32_t)(b * 8); };
    auto mbE = [&](int b) { return sb + 24u + (uint32_t)(b * 8); };
    auto aHb = [&](int b) { return sb + OFF_A + (uint32_t)(b * 16384); };
    auto aLb = [&](int b) { return sb + OFF_A + (uint32_t)(b * 16384 + 8192); };
    auto bHb = [&](int b) { return sb + OFF_B + (uint32_t)(b * 32768); };
    auto bLb = [&](int b) { return sb + OFF_B + (uint32_t)(b * 32768 + 16384); };

    if (tid == 0) {
#pragma unroll
        for (int b = 0; b < DEPTH; ++b) {
            MBARRIER_INIT(mbF(b), PT);
            MBARRIER_INIT(mbE(b), PT);
        }
    }

    // ---- load block inputs (all 512 threads) ----
#pragma unroll
    for (int j = 0; j < 4; ++j) {              // s -> transposed [u][65]
        int i = tid + j * THREADS;             // 2048 float4 slots
        int n = i >> 5, c4 = i & 31;
        float4 v = *(const float4*)(node_vec + (size_t)(nb + n) * 480 + c4 * 4);
        sT[(c4 * 4 + 0) * 65 + n] = v.x;
        sT[(c4 * 4 + 1) * 65 + n] = v.y;
        sT[(c4 * 4 + 2) * 65 + n] = v.z;
        sT[(c4 * 4 + 3) * 65 + n] = v.w;
    }
    {                                          // attr -> [n][36]
        int n = tid >> 3, c4 = tid & 7;
        *(float4*)(attrS + n * 36 + c4 * 4) =
            *(const float4*)(attr_g + (size_t)(nb + n) * NV + c4 * 4);
    }
    if (tid < 256) ((float4*)w3S)[tid] = ((const float4*)W3)[tid];
    if (tid < 128) b1S[tid] = b1s[tid];
    if (tid < 32) { b2S[tid] = b2[tid]; b3S[tid] = b3[tid]; w4S[tid] = W4[tid]; }
    if (tid == 0) b4S[0] = b4[0];
    __syncthreads();

    if (producer) {
        // ==================== producer: stage 1 fills ====================
        for (int g = 0; g < NCHUNK; ++g) {
            const int b = g % DEPTH;
            if (g >= DEPTH) { MBARRIER_WAIT_PARITY(mbE(b), (g / DEPTH - 1) & 1); }
            fillA(g, aHb(b), aLb(b), sT, attrS, ptid);
            fillB<128>(g, bHb(b), bLb(b), g_W1T_hi, g_W1T_lo, ptid);
            MBARRIER_ARRIVE(mbF(b));
        }
        BARX();   // wait for epilogue-1 (aT written into sT)
        // ==================== producer: stage 2 fills ====================
        for (int g = NCHUNK; g < 2 * NCHUNK; ++g) {
            const int b = g % DEPTH;
            MBARRIER_WAIT_PARITY(mbE(b), (g / DEPTH - 1) & 1);
            fillA(g - NCHUNK, aHb(b), aLb(b), sT, attrS, ptid);
            fillB<32>(g - NCHUNK, bHb(b), bLb(b), g_W2T_hi, g_W2T_lo, ptid);
            MBARRIER_ARRIVE(mbF(b));
        }
        BARX();   // join before tail
    } else {
        // ldmatrix per-lane offsets
        const uint32_t rowA = (uint32_t)((((lane >> 3) & 1) << 3) + (lane & 7));
        const uint32_t colA = (uint32_t)((lane >> 4) << 4);
        const uint32_t rowB = (uint32_t)(((lane >> 4) << 3) + (lane & 7));
        const uint32_t colB = (uint32_t)(((lane >> 3) & 1) << 4);

        // ==================== consumer: stage 1 ====================
        {
            const int m0 = (wid >> 2) * 32;
            const int n0 = (wid & 3) * 32;
            float    accF[2][4][4];
            uint32_t accC[2][4][2];
#pragma unroll
            for (int a = 0; a < 2; ++a)
#pragma unroll
                for (int b = 0; b < 4; ++b) {
#pragma unroll
                    for (int q = 0; q < 4; ++q) accF[a][b][q] = 0.0f;
                    accC[a][b][0] = 0u; accC[a][b][1] = 0u;
                }

            for (int g = 0; g < NCHUNK; ++g) {
                const int b = g % DEPTH;
                MBARRIER_WAIT_PARITY(mbF(b), (g / DEPTH) & 1);
                const uint32_t aHt = aHb(b), aLt = aLb(b);
                const uint32_t bHt = bHb(b), bLt = bLb(b);
#pragma unroll
                for (int ks = 0; ks < 4; ++ks) {
                    uint32_t aH[2][4], aL[2][4], bH[2][4], bL[2][4];
#pragma unroll
                    for (int mf = 0; mf < 2; ++mf) {
                        uint32_t off = swz((uint32_t)((m0 + mf * 16 + rowA) * 128 + ks * 32 + colA));
                        ldsm4(aH[mf], aHt + off);
                        ldsm4(aL[mf], aLt + off);
                    }
#pragma unroll
                    for (int nbk = 0; nbk < 2; ++nbk) {
                        uint32_t off = swz((uint32_t)((n0 + nbk * 16 + rowB) * 128 + ks * 32 + colB));
                        ldsm4(bH[nbk], bHt + off);
                        ldsm4(bL[nbk], bLt + off);
                    }
#pragma unroll
                    for (int mf = 0; mf < 2; ++mf)
#pragma unroll
                        for (int nf = 0; nf < 4; ++nf) {
                            uint32_t h0 = bH[nf >> 1][(nf & 1) * 2], h1 = bH[nf >> 1][(nf & 1) * 2 + 1];
                            uint32_t l0 = bL[nf >> 1][(nf & 1) * 2], l1 = bL[nf >> 1][(nf & 1) * 2 + 1];
                            mma_f32(accF[mf][nf], aH[mf], h0, h1);
                            mma_f16(accC[mf][nf], aH[mf], l0, l1);
                            mma_f16(accC[mf][nf], aL[mf], h0, h1);
                        }
                }
                MBARRIER_ARRIVE(mbE(b));
            }

            // epilogue 1: silu(c + corr + b1) -> sT[w][node]
#pragma unroll
            for (int mf = 0; mf < 2; ++mf)
#pragma unroll
                for (int nf = 0; nf < 4; ++nf) {
                    int m = m0 + mf * 16 + (lane >> 2);
                    int w = n0 + nf * 8 + ((lane & 3) << 1);
                    float* cc = accF[mf][nf];
                    float2 p0 = __half22float2(*(__half2*)&accC[mf][nf][0]);
                    float2 p1 = __half22float2(*(__half2*)&accC[mf][nf][1]);
                    sT[w * 65 + m]           = silu_f(cc[0] + p0.x + b1S[w]);
                    sT[(w + 1) * 65 + m]     = silu_f(cc[1] + p0.y + b1S[w + 1]);
                    sT[w * 65 + m + 8]       = silu_f(cc[2] + p1.x + b1S[w]);
                    sT[(w + 1) * 65 + m + 8] = silu_f(cc[3] + p1.y + b1S[w + 1]);
                }
        }
        BARX();   // release producers to start stage-2 fills

        // ==================== consumer: stage 2 ====================
        {
            const int m0 = (wid >> 1) * 16;
            const int n0 = (wid & 1) * 16;
            float    accF[2][4];
            uint32_t accC[2][2];
#pragma unroll
            for (int b = 0; b < 2; ++b) {
#pragma unroll
                for (int q = 0; q < 4; ++q) accF[b][q] = 0.0f;
                accC[b][0] = 0u; accC[b][1] = 0u;
            }

            for (int g = NCHUNK; g < 2 * NCHUNK; ++g) {
                const int b = g % DEPTH;
                MBARRIER_WAIT_PARITY(mbF(b), (g / DEPTH) & 1);
                const uint32_t aHt = aHb(b), aLt = aLb(b);
                const uint32_t bHt = bHb(b), bLt = bLb(b);
#pragma unroll
                for (int ks = 0; ks < 4; ++ks) {
                    uint32_t aH[4], aL[4], bH[4], bL[4];
                    {
                        uint32_t off = swz((uint32_t)((m0 + rowA) * 128 + ks * 32 + colA));
                        ldsm4(aH, aHt + off);
                        ldsm4(aL, aLt + off);
                    }
                    {
                        uint32_t off = swz((uint32_t)((n0 + rowB) * 128 + ks * 32 + colB));
                        ldsm4(bH, bHt + off);
                        ldsm4(bL, bLt + off);
                    }
#pragma unroll
                    for (int nf = 0; nf < 2; ++nf) {
                        uint32_t h0 = bH[nf * 2], h1 = bH[nf * 2 + 1];
                        uint32_t l0 = bL[nf * 2], l1 = bL[nf * 2 + 1];
                        mma_f32(accF[nf], aH, h0, h1);
                        mma_f16(accC[nf], aH, l0, l1);
                        mma_f16(accC[nf], aL, h0, h1);
                    }
                }
                MBARRIER_ARRIVE(mbE(b));
            }

            // epilogue 2: h = c + corr + b2 -> hS[node][33]
#pragma unroll
            for (int nf = 0; nf < 2; ++nf) {
                int m = m0 + (lane >> 2);
                int w = n0 + nf * 8 + ((lane & 3) << 1);
                float* cc = accF[nf];
                float2 p0 = __half22float2(*(__half2*)&accC[nf][0]);
                float2 p1 = __half22float2(*(__half2*)&accC[nf][1]);
                hS[m * 33 + w]           = cc[0] + p0.x + b2S[w];
                hS[m * 33 + w + 1]       = cc[1] + p0.y + b2S[w + 1];
                hS[(m + 8) * 33 + w]     = cc[2] + p1.x + b2S[w];
                hS[(m + 8) * 33 + w + 1] = cc[3] + p1.y + b2S[w + 1];
            }
        }
        BARX();   // join before tail
    }

    // ======================= stage 3/4: 8 threads per node =======================
    {
        const int node  = tid >> 3;
        const int lane8 = tid & 7;
        const float inv32 = 0.17677669529663687f;  // 1/sqrt(32)
        float o = 0.0f;
#pragma unroll
        for (int j = 0; j < 4; ++j) {
            int w = lane8 + j * 8;
            float z = 0.0f;
#pragma unroll
            for (int k = 0; k < 32; ++k) z += hS[node * 33 + k] * w3S[k * 32 + w];
            z = z * inv32 + b3S[w];
            o += silu_f(z) * (w4S[w] * inv32);
        }
#pragma unroll
        for (int m = 1; m < 8; m <<= 1)
            o += __shfl_xor_sync(0xffffffff, o, m);
        if (lane8 == 0) out[nb + node] = o + b4S[0];
    }
}

// ============================================================================
extern "C" void kernel_launch(void* const* d_in, const int* in_sizes, int n_in,
                              void* d_out, int out_size) {
    const float* node_vec = (const float*)d_in[0];
    const float* attr     = (const float*)d_in[1];
    const float* W1s      = (const float*)d_in[2];
    const float* b1s      = (const float*)d_in[3];
    // d_in[4..7] = W1g, b1g, W1v1, W1v2 : dead in the reference
    const float* W2       = (const float*)d_in[8];
    const float* b2       = (const float*)d_in[9];
    const float* W3       = (const float*)d_in[10];
    const float* b3       = (const float*)d_in[11];
    const float* W4       = (const float*)d_in[12];
    const float* b4       = (const float*)d_in[13];
    float* out = (float*)d_out;

    const int N = out_size;                    // 8192

    prep_all<<<320, 256>>>(W1s, W2);

    cudaFuncSetAttribute(eq_hmma, cudaFuncAttributeMaxDynamicSharedMemorySize,
                         (int)SMEM_BYTES);
    eq_hmma<<<N / MT, THREADS, SMEM_BYTES>>>(node_vec, attr, b1s, b2, W3, b3, W4, b4, out);
}

// round 7
// speedup vs baseline: 2.4500x; 1.0161x over previous
#include <cuda_runtime.h>
#include <cuda_fp16.h>
#include <cstdint>

// ============================================================================
// Problem constants
// ============================================================================
#define NU 128         // MUL0
#define NV 32          // A
#define KTOT 4096      // NU*NV
#define MT 64          // nodes per block
#define NCHUNK 64      // KTOT/64 per stage
#define THREADS 512    // 8 consumer warps + 8 producer warps
#define PT 256         // producer thread count
#define DEPTH 3        // pipeline buffers

// pre-transposed / hi-lo split weights (scale 1/8 folded in; A side gets 1/8 too)
__device__ __align__(16) __half g_W1T_hi[NU * KTOT];
__device__ __align__(16) __half g_W1T_lo[NU * KTOT];
__device__ __align__(16) __half g_W2T_hi[NV * KTOT];
__device__ __align__(16) __half g_W2T_lo[NV * KTOT];

// ---- smem layout (bytes) ----
constexpr uint32_t OFF_A    = 1024;       // 3 bufs x (hi 8KB + lo 8KB) = 49152 (tail: psum 32KB)
constexpr uint32_t OFF_B    = 50176;      // 3 bufs x (hi 16KB + lo 16KB) = 98304
constexpr uint32_t OFF_S    = 148480;     // sT / aT fp32 [128u][65] = 33280
constexpr uint32_t OFF_ATTR = 181760;     // attr fp32 [64n][36] = 9216
constexpr uint32_t OFF_H    = 190976;     // h fp32 [64n][33] = 8448
constexpr uint32_t OFF_W3   = 199424;     // 4096
constexpr uint32_t OFF_B1   = 203520;     // 512
constexpr uint32_t OFF_B2   = 204032;     // 128
constexpr uint32_t OFF_B3   = 204160;     // 128
constexpr uint32_t OFF_W4   = 204288;     // 128
constexpr uint32_t OFF_B4   = 204416;     // 16
constexpr uint32_t SMEM_BYTES = 204432;   // ~199.6 KB

extern __shared__ char smem_raw[];

__device__ __forceinline__ uint32_t smem_u32(const void* p) {
    uint32_t a;
    asm("{ .reg .u64 t; cvta.to.shared.u64 t, %1; cvt.u32.u64 %0, t; }" : "=r"(a) : "l"(p));
    return a;
}
__device__ __forceinline__ uint32_t swz(uint32_t o) { return o ^ ((o >> 3) & 0x70); }
__device__ __forceinline__ float silu_f(float x) { return x / (1.0f + __expf(-x)); }

#define STS128(r0, r1, r2, r3, sa) \
    asm volatile("st.shared.v4.b32 [%0], {%1, %2, %3, %4};" \
                 :: "r"(sa), "r"(r0), "r"(r1), "r"(r2), "r"(r3) : "memory")

// named barriers: FULL_b = 1+b, EMPTY_b = 4+b, stage/join barrier = 15
#define BAR_SYNC_ID(id)   asm volatile("bar.sync %0, %1;"   :: "r"(id), "n"(THREADS) : "memory")
#define BAR_ARRIVE_ID(id) asm volatile("bar.arrive %0, %1;" :: "r"(id), "n"(THREADS) : "memory")
#define BARX() asm volatile("bar.sync 15, %0;" :: "n"(THREADS) : "memory")

#define CP_ASYNC16(dst, src) \
    asm volatile("cp.async.cg.shared.global [%0], [%1], 16;" :: "r"(dst), "l"(src))
#define CP_ASYNC_WAIT_ALL() asm volatile("cp.async.wait_all;" ::: "memory")

__device__ __forceinline__ void ldsm4(uint32_t* r, uint32_t addr) {
    asm volatile("ldmatrix.sync.aligned.m8n8.x4.shared.b16 {%0,%1,%2,%3}, [%4];"
                 : "=r"(r[0]), "=r"(r[1]), "=r"(r[2]), "=r"(r[3]) : "r"(addr));
}
// main pass: fp16 operands, fp32 accumulators
__device__ __forceinline__ void mma_f32(float* c, const uint32_t* a,
                                        uint32_t b0, uint32_t b1) {
    asm volatile(
        "mma.sync.aligned.m16n8k16.row.col.f32.f16.f16.f32 "
        "{%0,%1,%2,%3}, {%4,%5,%6,%7}, {%8,%9}, {%0,%1,%2,%3};"
        : "+f"(c[0]), "+f"(c[1]), "+f"(c[2]), "+f"(c[3])
        : "r"(a[0]), "r"(a[1]), "r"(a[2]), "r"(a[3]), "r"(b0), "r"(b1));
}
// correction passes: fp16 operands, fp16 accumulators
__device__ __forceinline__ void mma_f16(uint32_t* c, const uint32_t* a,
                                        uint32_t b0, uint32_t b1) {
    asm volatile(
        "mma.sync.aligned.m16n8k16.row.col.f16.f16.f16.f16 "
        "{%0,%1}, {%2,%3,%4,%5}, {%6,%7}, {%0,%1};"
        : "+r"(c[0]), "+r"(c[1])
        : "r"(a[0]), "r"(a[1]), "r"(a[2]), "r"(a[3]), "r"(b0), "r"(b1));
}

// ============================================================================
// merged prep kernel: W[k][w] fp32 -> W^T[w][k] fp16 hi/lo, 1/8 scale folded
// ============================================================================
__global__ void __launch_bounds__(256) prep_all(const float* __restrict__ W1s,
                                                const float* __restrict__ W2) {
    __shared__ float tile[64][65];
    const int t = threadIdx.x;
    const int b = blockIdx.x;
    if (b < 256) {
        const int k0 = (b & 127) * 32;
        const int w0 = (b >> 7) * 64;
#pragma unroll
        for (int it = 0; it < 2; ++it) {
            int s = it * 256 + t;
            int r = s >> 4, q = s & 15;
            float4 v = *(const float4*)(W1s + (size_t)(k0 + r) * NU + w0 + q * 4);
            tile[r][q * 4 + 0] = v.x; tile[r][q * 4 + 1] = v.y;
            tile[r][q * 4 + 2] = v.z; tile[r][q * 4 + 3] = v.w;
        }
        __syncthreads();
        const int w = t >> 2, kq = t & 3;
        uint32_t hb[4], lb[4];
#pragma unroll
        for (int q = 0; q < 4; ++q) {
            float x0 = tile[kq * 8 + 2 * q][w]     * 0.125f;
            float x1 = tile[kq * 8 + 2 * q + 1][w] * 0.125f;
            __half h0 = __float2half_rn(x0), h1 = __float2half_rn(x1);
            float r0 = x0 - __half2float(h0), r1 = x1 - __half2float(h1);
            __half l0 = __float2half_rn(r0), l1 = __float2half_rn(r1);
            hb[q] = (uint32_t)__half_as_ushort(h0) | ((uint32_t)__half_as_ushort(h1) << 16);
            lb[q] = (uint32_t)__half_as_ushort(l0) | ((uint32_t)__half_as_ushort(l1) << 16);
        }
        ((uint4*)(g_W1T_hi + (size_t)(w0 + w) * KTOT + k0))[kq] =
            make_uint4(hb[0], hb[1], hb[2], hb[3]);
        ((uint4*)(g_W1T_lo + (size_t)(w0 + w) * KTOT + k0))[kq] =
            make_uint4(lb[0], lb[1], lb[2], lb[3]);
    } else {
        const int k0 = (b - 256) * 64;
#pragma unroll
        for (int it = 0; it < 2; ++it) {
            int s = it * 256 + t;
            int r = s >> 3, q = s & 7;
            float4 v = *(const float4*)(W2 + (size_t)(k0 + r) * NV + q * 4);
            tile[r][q * 4 + 0] = v.x; tile[r][q * 4 + 1] = v.y;
            tile[r][q * 4 + 2] = v.z; tile[r][q * 4 + 3] = v.w;
        }
        __syncthreads();
        const int w = t >> 3, kq = t & 7;
        uint32_t hb[4], lb[4];
#pragma unroll
        for (int q = 0; q < 4; ++q) {
            float x0 = tile[kq * 8 + 2 * q][w]     * 0.125f;
            float x1 = tile[kq * 8 + 2 * q + 1][w] * 0.125f;
            __half h0 = __float2half_rn(x0), h1 = __float2half_rn(x1);
            float r0 = x0 - __half2float(h0), r1 = x1 - __half2float(h1);
            __half l0 = __float2half_rn(r0), l1 = __float2half_rn(r1);
            hb[q] = (uint32_t)__half_as_ushort(h0) | ((uint32_t)__half_as_ushort(h1) << 16);
            lb[q] = (uint32_t)__half_as_ushort(l0) | ((uint32_t)__half_as_ushort(l1) << 16);
        }
        ((uint4*)(g_W2T_hi + (size_t)w * KTOT + k0))[kq] =
            make_uint4(hb[0], hb[1], hb[2], hb[3]);
        ((uint4*)(g_W2T_lo + (size_t)w * KTOT + k0))[kq] =
            make_uint4(lb[0], lb[1], lb[2], lb[3]);
    }
}

// ============================================================================
// tile fills (producer warps, ptid in [0,256))
// ============================================================================
__device__ __forceinline__ void fillA(int c, uint32_t aH, uint32_t aL,
                                      const float* srcT, const float* attrS, int ptid) {
#pragma unroll
    for (int j = 0; j < 2; ++j) {
        int slot = ptid + j * PT;            // 0..511
        int n = slot >> 3, kg = slot & 7;
        int u = (c << 1) + (kg >> 2);
        int vb = (kg & 3) << 3;
        float su = srcT[u * 65 + n] * 0.125f;      // A-side scale
        float4 a0 = *(const float4*)(attrS + n * 36 + vb);
        float4 a1 = *(const float4*)(attrS + n * 36 + vb + 4);
        float v[8] = {a0.x, a0.y, a0.z, a0.w, a1.x, a1.y, a1.z, a1.w};
        uint32_t hb[4], lb[4];
#pragma unroll
        for (int q = 0; q < 4; ++q) {
            float x0 = su * v[2 * q], x1 = su * v[2 * q + 1];
            __half h0 = __float2half_rn(x0), h1 = __float2half_rn(x1);
            float r0 = x0 - __half2float(h0), r1 = x1 - __half2float(h1);
            __half l0 = __float2half_rn(r0), l1 = __float2half_rn(r1);
            hb[q] = (uint32_t)__half_as_ushort(h0) | ((uint32_t)__half_as_ushort(h1) << 16);
            lb[q] = (uint32_t)__half_as_ushort(l0) | ((uint32_t)__half_as_ushort(l1) << 16);
        }
        uint32_t sw = swz((uint32_t)(n * 128 + (kg << 4)));
        STS128(hb[0], hb[1], hb[2], hb[3], aH + sw);
        STS128(lb[0], lb[1], lb[2], lb[3], aL + sw);
    }
}

template <int BROWS>
__device__ __forceinline__ void fillB_async(int c, uint32_t bH, uint32_t bL,
                                            const __half* gHi, const __half* gLo, int ptid) {
#pragma unroll
    for (int j = 0; j < (BROWS * 16) / PT; ++j) {
        int slot = ptid + j * PT;            // [0, BROWS*16)
        int hl = (slot >= BROWS * 8) ? 1 : 0;
        int s2 = slot - hl * BROWS * 8;
        int row = s2 >> 3, kg = s2 & 7;
        const char* src = (const char*)(hl ? gLo : gHi) +
                          (size_t)(row * 512 + c * 8 + kg) * 16;
        uint32_t sw = swz((uint32_t)(row * 128 + (kg << 4)));
        CP_ASYNC16((hl ? bL : bH) + sw, src);
    }
}

// ============================================================================
// main fused kernel: one block = 64 nodes; warps 0-7 MMA, warps 8-15 fill
// 3-deep named-barrier pipeline, global chunk index g in [0,128)
// ============================================================================
__global__ void __launch_bounds__(THREADS, 1)
eq_hmma(const float* __restrict__ node_vec,   // [N,480]
        const float* __restrict__ attr_g,     // [N,32]
        const float* __restrict__ b1s,        // [128]
        const float* __restrict__ b2,         // [32]
        const float* __restrict__ W3,         // [32,32]
        const float* __restrict__ b3,         // [32]
        const float* __restrict__ W4,         // [32]
        const float* __restrict__ b4,         // [1]
        float* __restrict__ out)              // [N]
{
    const int tid  = threadIdx.x;
    const int wid  = tid >> 5;
    const int lane = tid & 31;
    const int nb   = blockIdx.x * MT;
    const uint32_t sb = smem_u32(smem_raw);
    const bool producer = (wid >= 8);
    const int ptid = tid - 256;

    float* sT    = (float*)(smem_raw + OFF_S);     // [u][65]
    float* attrS = (float*)(smem_raw + OFF_ATTR);  // [n][36]
    float* hS    = (float*)(smem_raw + OFF_H);     // [n][33]
    float* psum  = (float*)(smem_raw + OFF_A);     // tail reuse: [ksg][64m][32n]
    float* w3S   = (float*)(smem_raw + OFF_W3);
    float* b1S   = (float*)(smem_raw + OFF_B1);
    float* b2S   = (float*)(smem_raw + OFF_B2);
    float* b3S   = (float*)(smem_raw + OFF_B3);
    float* w4S   = (float*)(smem_raw + OFF_W4);
    float* b4S   = (float*)(smem_raw + OFF_B4);

    auto aHb = [&](int b) { return sb + OFF_A + (uint32_t)(b * 16384); };
    auto aLb = [&](int b) { return sb + OFF_A + (uint32_t)(b * 16384 + 8192); };
    auto bHb = [&](int b) { return sb + OFF_B + (uint32_t)(b * 32768); };
    auto bLb = [&](int b) { return sb + OFF_B + (uint32_t)(b * 32768 + 16384); };

    // ---- load block inputs (all 512 threads) ----
#pragma unroll
    for (int j = 0; j < 4; ++j) {              // s -> transposed [u][65]
        int i = tid + j * THREADS;             // 2048 float4 slots
        int n = i >> 5, c4 = i & 31;
        float4 v = *(const float4*)(node_vec + (size_t)(nb + n) * 480 + c4 * 4);
        sT[(c4 * 4 + 0) * 65 + n] = v.x;
        sT[(c4 * 4 + 1) * 65 + n] = v.y;
        sT[(c4 * 4 + 2) * 65 + n] = v.z;
        sT[(c4 * 4 + 3) * 65 + n] = v.w;
    }
    {                                          // attr -> [n][36]
        int n = tid >> 3, c4 = tid & 7;
        *(float4*)(attrS + n * 36 + c4 * 4) =
            *(const float4*)(attr_g + (size_t)(nb + n) * NV + c4 * 4);
    }
    if (tid < 256) ((float4*)w3S)[tid] = ((const float4*)W3)[tid];
    if (tid < 128) b1S[tid] = b1s[tid];
    if (tid < 32) { b2S[tid] = b2[tid]; b3S[tid] = b3[tid]; w4S[tid] = W4[tid]; }
    if (tid == 0) b4S[0] = b4[0];
    __syncthreads();

    if (producer) {
        // ==================== producer: stage 1 fills ====================
        for (int g = 0; g < NCHUNK; ++g) {
            const int b = g % DEPTH;
            if (g >= DEPTH) BAR_SYNC_ID(4 + b);
            fillB_async<128>(g, bHb(b), bLb(b), g_W1T_hi, g_W1T_lo, ptid);
            fillA(g, aHb(b), aLb(b), sT, attrS, ptid);
            CP_ASYNC_WAIT_ALL();
            BAR_ARRIVE_ID(1 + b);
        }
        BARX();   // wait for epilogue-1 (aT written into sT)
        // ==================== producer: stage 2 fills ====================
        for (int g = NCHUNK; g < 2 * NCHUNK; ++g) {
            const int b = g % DEPTH;
            BAR_SYNC_ID(4 + b);
            fillB_async<32>(g - NCHUNK, bHb(b), bLb(b), g_W2T_hi, g_W2T_lo, ptid);
            fillA(g - NCHUNK, aHb(b), aLb(b), sT, attrS, ptid);
            CP_ASYNC_WAIT_ALL();
            BAR_ARRIVE_ID(1 + b);
        }
    } else {
        // ldmatrix per-lane offsets
        const uint32_t rowA = (uint32_t)((((lane >> 3) & 1) << 3) + (lane & 7));
        const uint32_t colA = (uint32_t)((lane >> 4) << 4);
        const uint32_t rowB = (uint32_t)(((lane >> 4) << 3) + (lane & 7));
        const uint32_t colB = (uint32_t)(((lane >> 3) & 1) << 4);

        // ==================== consumer: stage 1 ====================
        {
            const int m0 = (wid >> 2) * 32;
            const int n0 = (wid & 3) * 32;
            float    accF[2][4][4];
            uint32_t accC[2][4][2];
#pragma unroll
            for (int a = 0; a < 2; ++a)
#pragma unroll
                for (int b = 0; b < 4; ++b) {
#pragma unroll
                    for (int q = 0; q < 4; ++q) accF[a][b][q] = 0.0f;
                    accC[a][b][0] = 0u; accC[a][b][1] = 0u;
                }

            for (int g = 0; g < NCHUNK; ++g) {
                const int b = g % DEPTH;
                BAR_SYNC_ID(1 + b);
                const uint32_t aHt = aHb(b), aLt = aLb(b);
                const uint32_t bHt = bHb(b), bLt = bLb(b);
#pragma unroll
                for (int ks = 0; ks < 4; ++ks) {
                    uint32_t aH[2][4], aL[2][4], bH[2][4], bL[2][4];
#pragma unroll
                    for (int mf = 0; mf < 2; ++mf) {
                        uint32_t off = swz((uint32_t)((m0 + mf * 16 + rowA) * 128 + ks * 32 + colA));
                        ldsm4(aH[mf], aHt + off);
                        ldsm4(aL[mf], aLt + off);
                    }
#pragma unroll
                    for (int nbk = 0; nbk < 2; ++nbk) {
                        uint32_t off = swz((uint32_t)((n0 + nbk * 16 + rowB) * 128 + ks * 32 + colB));
                        ldsm4(bH[nbk], bHt + off);
                        ldsm4(bL[nbk], bLt + off);
                    }
#pragma unroll
                    for (int mf = 0; mf < 2; ++mf)
#pragma unroll
                        for (int nf = 0; nf < 4; ++nf) {
                            uint32_t h0 = bH[nf >> 1][(nf & 1) * 2], h1 = bH[nf >> 1][(nf & 1) * 2 + 1];
                            uint32_t l0 = bL[nf >> 1][(nf & 1) * 2], l1 = bL[nf >> 1][(nf & 1) * 2 + 1];
                            mma_f32(accF[mf][nf], aH[mf], h0, h1);
                            mma_f16(accC[mf][nf], aH[mf], l0, l1);
                            mma_f16(accC[mf][nf], aL[mf], h0, h1);
                        }
                }
                BAR_ARRIVE_ID(4 + b);
            }

            // epilogue 1: silu(c + corr + b1) -> sT[w][node]
            // (safe: producers finished fillA(63) reading sT before consumers saw FULL(63))
#pragma unroll
            for (int mf = 0; mf < 2; ++mf)
#pragma unroll
                for (int nf = 0; nf < 4; ++nf) {
                    int m = m0 + mf * 16 + (lane >> 2);
                    int w = n0 + nf * 8 + ((lane & 3) << 1);
                    float* cc = accF[mf][nf];
                    float2 p0 = __half22float2(*(__half2*)&accC[mf][nf][0]);
                    float2 p1 = __half22float2(*(__half2*)&accC[mf][nf][1]);
                    sT[w * 65 + m]           = silu_f(cc[0] + p0.x + b1S[w]);
                    sT[(w + 1) * 65 + m]     = silu_f(cc[1] + p0.y + b1S[w + 1]);
                    sT[w * 65 + m + 8]       = silu_f(cc[2] + p1.x + b1S[w]);
                    sT[(w + 1) * 65 + m + 8] = silu_f(cc[3] + p1.y + b1S[w + 1]);
                }
        }
        BARX();   // release producers to start stage-2 fills

        // ======== consumer: stage 2 — k-split: warp = (m-half, ks-slice) ========
        {
            const int mg  = wid >> 2;          // 0..1  -> m0 = mg*32
            const int ksg = wid & 3;           // 0..3  -> k-slice ksg*16
            const int m0  = mg * 32;
            float    accF[2][4][4];
            uint32_t accC[2][4][2];
#pragma unroll
            for (int a = 0; a < 2; ++a)
#pragma unroll
                for (int b = 0; b < 4; ++b) {
#pragma unroll
                    for (int q = 0; q < 4; ++q) accF[a][b][q] = 0.0f;
                    accC[a][b][0] = 0u; accC[a][b][1] = 0u;
                }

            for (int g = NCHUNK; g < 2 * NCHUNK; ++g) {
                const int b = g % DEPTH;
                BAR_SYNC_ID(1 + b);
                const uint32_t aHt = aHb(b), aLt = aLb(b);
                const uint32_t bHt = bHb(b), bLt = bLb(b);
                uint32_t aH[2][4], aL[2][4], bH[2][4], bL[2][4];
#pragma unroll
                for (int mf = 0; mf < 2; ++mf) {
                    uint32_t off = swz((uint32_t)((m0 + mf * 16 + rowA) * 128 + ksg * 32 + colA));
                    ldsm4(aH[mf], aHt + off);
                    ldsm4(aL[mf], aLt + off);
                }
#pragma unroll
                for (int ng = 0; ng < 2; ++ng) {
                    uint32_t off = swz((uint32_t)((ng * 16 + rowB) * 128 + ksg * 32 + colB));
                    ldsm4(bH[ng], bHt + off);
                    ldsm4(bL[ng], bLt + off);
                }
#pragma unroll
                for (int mf = 0; mf < 2; ++mf)
#pragma unroll
                    for (int nf = 0; nf < 4; ++nf) {
                        uint32_t h0 = bH[nf >> 1][(nf & 1) * 2], h1 = bH[nf >> 1][(nf & 1) * 2 + 1];
                        uint32_t l0 = bL[nf >> 1][(nf & 1) * 2], l1 = bL[nf >> 1][(nf & 1) * 2 + 1];
                        mma_f32(accF[mf][nf], aH[mf], h0, h1);
                        mma_f16(accC[mf][nf], aH[mf], l0, l1);
                        mma_f16(accC[mf][nf], aL[mf], h0, h1);
                    }
                BAR_ARRIVE_ID(4 + b);
            }

            // write k-partials to psum (after join below)
            BARX();   // pairs with producers' first post-loop BARX; buffers now dead
#pragma unroll
            for (int mf = 0; mf < 2; ++mf)
#pragma unroll
                for (int nf = 0; nf < 4; ++nf) {
                    int m = m0 + mf * 16 + (lane >> 2);
                    int w = nf * 8 + ((lane & 3) << 1);
                    float* cc = accF[mf][nf];
                    float2 p0 = __half22float2(*(__half2*)&accC[mf][nf][0]);
                    float2 p1 = __half22float2(*(__half2*)&accC[mf][nf][1]);
                    psum[(ksg * 64 + m) * 32 + w]           = cc[0] + p0.x;
                    psum[(ksg * 64 + m) * 32 + w + 1]       = cc[1] + p0.y;
                    psum[(ksg * 64 + m + 8) * 32 + w]       = cc[2] + p1.x;
                    psum[(ksg * 64 + m + 8) * 32 + w + 1]   = cc[3] + p1.y;
                }
        }
    }
    if (producer) BARX();   // pairs with consumers' post-stage-2 BARX
    BARX();                 // all: partials written

    // reduce 4 k-partials + bias -> hS (all 512 threads)
#pragma unroll
    for (int j = 0; j < 4; ++j) {
        int idx = tid + j * THREADS;           // [0, 2048)
        int m = idx >> 5, n = idx & 31;
        float h = psum[m * 32 + n] + psum[(64 + m) * 32 + n]
                + psum[(128 + m) * 32 + n] + psum[(192 + m) * 32 + n] + b2S[n];
        hS[m * 33 + n] = h;
    }
    BARX();

    // ======================= stage 3/4: 8 threads per node =======================
    {
        const int node  = tid >> 3;
        const int lane8 = tid & 7;
        const float inv32 = 0.17677669529663687f;  // 1/sqrt(32)
        float o = 0.0f;
#pragma unroll
        for (int j = 0; j < 4; ++j) {
            int w = lane8 + j * 8;
            float z = 0.0f;
#pragma unroll
            for (int k = 0; k < 32; ++k) z += hS[node * 33 + k] * w3S[k * 32 + w];
            z = z * inv32 + b3S[w];
            o += silu_f(z) * (w4S[w] * inv32);
        }
#pragma unroll
        for (int m = 1; m < 8; m <<= 1)
            o += __shfl_xor_sync(0xffffffff, o, m);
        if (lane8 == 0) out[nb + node] = o + b4S[0];
    }
}

// ============================================================================
extern "C" void kernel_launch(void* const* d_in, const int* in_sizes, int n_in,
                              void* d_out, int out_size) {
    const float* node_vec = (const float*)d_in[0];
    const float* attr     = (const float*)d_in[1];
    const float* W1s      = (const float*)d_in[2];
    const float* b1s      = (const float*)d_in[3];
    // d_in[4..7] = W1g, b1g, W1v1, W1v2 : dead in the reference
    const float* W2       = (const float*)d_in[8];
    const float* b2       = (const float*)d_in[9];
    const float* W3       = (const float*)d_in[10];
    const float* b3       = (const float*)d_in[11];
    const float* W4       = (const float*)d_in[12];
    const float* b4       = (const float*)d_in[13];
    float* out = (float*)d_out;

    const int N = out_size;                    // 8192

    prep_all<<<320, 256>>>(W1s, W2);

    cudaFuncSetAttribute(eq_hmma, cudaFuncAttributeMaxDynamicSharedMemorySize,
                         (int)SMEM_BYTES);
    eq_hmma<<<N / MT, THREADS, SMEM_BYTES>>>(node_vec, attr, b1s, b2, W3, b3, W4, b4, out);
}